// round 10
// baseline (speedup 1.0000x reference)
#include <cuda_runtime.h>

// ---------------------------------------------------------------------------
// FiSHAttention — round 10 (resubmit of R8/R9; broker timeouts, never ran).
// R7 baseline: 1787.9us, rel_err 3.3e-7. K1=439us (fma 45.7%), K2~1085us.
// Model: K2 E-phase is MUFU-bound (100M expf @ 0.5 MUFU/cyc/SM ~ 830us).
// Fix: logits computed directly in log2 domain (mix weights pre-scaled by
// log2e), then polynomial 2^f + exponent-bit injection — all fma/alu pipe.
//   K1: fused GEMM  y = x @ [w_qkv(q,k rows 0:512); w_v]^T  -> QS,KS,VS scatter
//   K2: fused flash attention, S[k]=QK^T shared across 12 heads,
//       softmax WITHOUT max-subtraction (logits provably tiny), PV accumulate
//   K3: GEMM out = AO @ w_proj^T + b_proj
// ---------------------------------------------------------------------------

constexpr int BATCH = 8;
constexpr int SEQ   = 1024;
constexpr int DIMS  = 768;
constexpr int NH    = 12;   // local heads
constexpr int NG    = 4;    // global heads
constexpr int HD    = 64;   // head dim
constexpr int TOK   = BATCH * SEQ;          // 8192

// scratch (static device memory — no allocations allowed)
__device__ float g_QS[BATCH * NG * SEQ * HD];   // (b,k,n,d) scaled by 1/8
__device__ float g_KS[BATCH * NG * SEQ * HD];   // (b,k,n,d)
__device__ float g_VS[BATCH * NH * SEQ * HD];   // (b,h,n,d)
__device__ float g_AO[TOK * DIMS];              // (token, h*64+d)

// fast 2^y on the fma/alu pipes (no MUFU). Valid for |y| < ~60.
// n = rint(y) via 1.5*2^23 magic add (ulp=1 in that binade -> RNE rint).
// f = y-n in [-0.5,0.5]; degree-5 Taylor of 2^f (max rel err ~3.5e-6);
// scale by 2^n via integer exponent add (p in [0.70,1.42] -> safe).
__device__ __forceinline__ float exp2_fast(float y) {
    float t = y + 12582912.0f;                 // 1.5 * 2^23
    int   n = __float_as_int(t) - 0x4B400000;  // signed integer part
    float f = y - (t - 12582912.0f);           // f in [-0.5, 0.5]
    float p =              0.0013333558f;
    p = fmaf(p, f,         0.0096181291f);
    p = fmaf(p, f,         0.0555041087f);
    p = fmaf(p, f,         0.2402265069f);
    p = fmaf(p, f,         0.6931471806f);
    p = fmaf(p, f,         1.0f);
    return __int_as_float(__float_as_int(p) + (n << 23));
}

// ---------------------------------------------------------------------------
// Tiled SGEMM: C[M x NC] = A[M x 768] @ B[NC x 768]^T
// BM=BN=128, BK=8, 256 threads, 8x8 micro-tile (split 4+4 to avoid conflicts)
// EPI==0: A=x, B=cat(w_qkv[0:512], w_v), scatter into QS/KS/VS
// EPI==1: A=g_AO, B=w_proj, C=out + bias
// ---------------------------------------------------------------------------
template <int EPI>
__global__ __launch_bounds__(256, 2) void k_sgemm(
    const float* __restrict__ A,
    const float* __restrict__ B0,
    const float* __restrict__ B1,
    const float* __restrict__ bias,
    float* __restrict__ Cout)
{
    __shared__ float As[8][128];
    __shared__ float Bs[8][128];

    const int t  = threadIdx.x;
    const int bm = blockIdx.x;
    const int bn = blockIdx.y;
    const int tx = t & 15;
    const int ty = t >> 4;
    const int lr = t >> 1;          // 0..127 row within tile
    const int lc = (t & 1) << 2;    // 0 or 4 (k offset)

    const float* Ap   = (EPI == 1) ? (const float*)g_AO : A;
    const float* Arow = Ap + (bm * 128 + lr) * DIMS + lc;
    const int    ncol = bn * 128 + lr;
    const float* Brow;
    if (EPI == 0)
        Brow = (ncol < 512) ? (B0 + ncol * DIMS + lc)
                            : (B1 + (ncol - 512) * DIMS + lc);
    else
        Brow = B0 + ncol * DIMS + lc;

    float acc[8][8];
#pragma unroll
    for (int i = 0; i < 8; i++)
#pragma unroll
        for (int j = 0; j < 8; j++) acc[i][j] = 0.f;

    for (int kt = 0; kt < DIMS; kt += 8) {
        float4 av = *reinterpret_cast<const float4*>(Arow + kt);
        float4 bv = *reinterpret_cast<const float4*>(Brow + kt);
        __syncthreads();
        As[lc + 0][lr] = av.x; As[lc + 1][lr] = av.y;
        As[lc + 2][lr] = av.z; As[lc + 3][lr] = av.w;
        Bs[lc + 0][lr] = bv.x; Bs[lc + 1][lr] = bv.y;
        Bs[lc + 2][lr] = bv.z; Bs[lc + 3][lr] = bv.w;
        __syncthreads();
#pragma unroll
        for (int kk = 0; kk < 8; kk++) {
            float a[8], bb[8];
            *reinterpret_cast<float4*>(&a[0])  = *reinterpret_cast<const float4*>(&As[kk][ty * 4]);
            *reinterpret_cast<float4*>(&a[4])  = *reinterpret_cast<const float4*>(&As[kk][64 + ty * 4]);
            *reinterpret_cast<float4*>(&bb[0]) = *reinterpret_cast<const float4*>(&Bs[kk][tx * 4]);
            *reinterpret_cast<float4*>(&bb[4]) = *reinterpret_cast<const float4*>(&Bs[kk][64 + tx * 4]);
#pragma unroll
            for (int i = 0; i < 8; i++)
#pragma unroll
                for (int j = 0; j < 8; j++)
                    acc[i][j] = fmaf(a[i], bb[j], acc[i][j]);
        }
    }

    // epilogue: rows {ih*64+ty*4+ii}, cols {jh*64+tx*4 .. +3} (float4-contiguous)
#pragma unroll
    for (int ih = 0; ih < 2; ih++)
#pragma unroll
        for (int ii = 0; ii < 4; ii++) {
            int m    = bm * 128 + ih * 64 + ty * 4 + ii;
            int bidx = m >> 10;
            int n    = m & 1023;
#pragma unroll
            for (int jh = 0; jh < 2; jh++) {
                int    c0 = bn * 128 + jh * 64 + tx * 4;
                float4 v  = make_float4(acc[ih * 4 + ii][jh * 4 + 0],
                                        acc[ih * 4 + ii][jh * 4 + 1],
                                        acc[ih * 4 + ii][jh * 4 + 2],
                                        acc[ih * 4 + ii][jh * 4 + 3]);
                if (EPI == 0) {
                    int d = c0 & 63;
                    if (c0 < 256) {
                        int k = c0 >> 6;
                        v.x *= 0.125f; v.y *= 0.125f; v.z *= 0.125f; v.w *= 0.125f;
                        *reinterpret_cast<float4*>(
                            &g_QS[(((bidx * NG + k) << 10) + n) * HD + d]) = v;
                    } else if (c0 < 512) {
                        int k = (c0 - 256) >> 6;
                        *reinterpret_cast<float4*>(
                            &g_KS[(((bidx * NG + k) << 10) + n) * HD + d]) = v;
                    } else {
                        int h = (c0 - 512) >> 6;
                        *reinterpret_cast<float4*>(
                            &g_VS[(((bidx * NH + h) << 10) + n) * HD + d]) = v;
                    }
                } else {
                    float4 b4 = *reinterpret_cast<const float4*>(&bias[c0]);
                    v.x += b4.x; v.y += b4.y; v.z += b4.z; v.w += b4.w;
                    *reinterpret_cast<float4*>(&Cout[m * DIMS + c0]) = v;
                }
            }
        }
}

// ---------------------------------------------------------------------------
// Fused flash attention.
// grid = (32 i-tiles, 8 batches), 256 threads, TM=TN=32.
// Per j-tile: S[k][32][32] computed once, mixed per head (groups of 4),
// 2^(mixed log2-logits) via exp2_fast (no MUFU), PV accumulated into smem O.
// smem: QiT 32K | KV(K^T then V) 32K | S 16.5K | E 16.5K | O 96K | misc
// ---------------------------------------------------------------------------
constexpr int SM_QIT  = 0;
constexpr int SM_KV   = SM_QIT + 4 * 64 * 32;      // 8192
constexpr int SM_S    = SM_KV + 4 * 64 * 32;       // 16384
constexpr int SM_E    = SM_S + 4 * 32 * 33;        // 20608
constexpr int SM_O    = SM_E + 4 * 32 * 33;        // 24832
constexpr int SM_DEN  = SM_O + 12 * 32 * 64;       // 49408
constexpr int SM_DRED = SM_DEN + 12 * 32;          // 49792
constexpr int SM_MIX  = SM_DRED + 256;             // 50048
constexpr int SM_TOT  = SM_MIX + 48;               // 50096 floats = 200384 B

__global__ __launch_bounds__(256, 1) void k_attn(const float* __restrict__ mix_logits)
{
    extern __shared__ float sm[];
    float* QiT  = sm + SM_QIT;
    float* KV   = sm + SM_KV;
    float* S    = sm + SM_S;
    float* E    = sm + SM_E;
    float* O    = sm + SM_O;
    float* den  = sm + SM_DEN;
    float* dred = sm + SM_DRED;
    float* mixs = sm + SM_MIX;

    const int t  = threadIdx.x;
    const int b  = blockIdx.y;
    const int i0 = blockIdx.x * 32;

    // head-mix softmax (deterministic eval mix), pre-scaled by log2(e) so the
    // E-phase computes logits directly in the base-2 domain.
    if (t < NH) {
        float m0 = mix_logits[t * 4 + 0], m1 = mix_logits[t * 4 + 1];
        float m2 = mix_logits[t * 4 + 2], m3 = mix_logits[t * 4 + 3];
        float mx = fmaxf(fmaxf(m0, m1), fmaxf(m2, m3));
        float e0 = __expf(m0 - mx), e1 = __expf(m1 - mx);
        float e2 = __expf(m2 - mx), e3 = __expf(m3 - mx);
        float inv = 1.4426950408889634f / (e0 + e1 + e2 + e3);  // log2e / sum
        mixs[t * 4 + 0] = e0 * inv; mixs[t * 4 + 1] = e1 * inv;
        mixs[t * 4 + 2] = e2 * inv; mixs[t * 4 + 3] = e3 * inv;
    }
    for (int e = t; e < 12 * 32 * 64 / 4; e += 256)
        reinterpret_cast<float4*>(O)[e] = make_float4(0.f, 0.f, 0.f, 0.f);
    for (int e = t; e < 12 * 32; e += 256) den[e] = 0.f;

    // load Q tile transposed: QiT[k][d][i]
    for (int e = t; e < 2048; e += 256) {
        int k  = e >> 9;
        int r  = (e >> 4) & 31;
        int c4 = (e & 15) << 2;
        float4 q = *reinterpret_cast<const float4*>(
            &g_QS[(((b * NG + k) << 10) + i0 + r) * HD + c4]);
        QiT[(k * 64 + c4 + 0) * 32 + r] = q.x;
        QiT[(k * 64 + c4 + 1) * 32 + r] = q.y;
        QiT[(k * 64 + c4 + 2) * 32 + r] = q.z;
        QiT[(k * 64 + c4 + 3) * 32 + r] = q.w;
    }
    __syncthreads();

    // thread mappings
    const int sk  = t >> 6;               // S: k head
    const int s64 = t & 63;
    const int si  = (s64 >> 3) << 2;      // S: i micro (4)
    const int sj  = (s64 & 7) << 2;       // S: j micro (4)

    const int eh  = (t & 127) >> 5;       // E: head-in-group
    const int ei  = t & 31;               // E: row
    const int ej0 = (t >> 7) << 4;        // E: j half (0/16)

    const int ph  = t >> 6;               // PV: head-in-group
    const int p64 = t & 63;
    const int pi  = (p64 >> 3) << 2;      // PV: i micro (4)
    const int pd  = (p64 & 7) << 3;       // PV: d micro (8)

    for (int jt = 0; jt < SEQ; jt += 32) {
        // K tile transposed into KV: KV[k][d][j]
        for (int e = t; e < 2048; e += 256) {
            int k  = e >> 9;
            int r  = (e >> 4) & 31;
            int c4 = (e & 15) << 2;
            float4 kv = *reinterpret_cast<const float4*>(
                &g_KS[(((b * NG + k) << 10) + jt + r) * HD + c4]);
            KV[(k * 64 + c4 + 0) * 32 + r] = kv.x;
            KV[(k * 64 + c4 + 1) * 32 + r] = kv.y;
            KV[(k * 64 + c4 + 2) * 32 + r] = kv.z;
            KV[(k * 64 + c4 + 3) * 32 + r] = kv.w;
        }
        __syncthreads();

        // S[k][i][j] = sum_d Q[i,d] K[j,d]
        {
            float acc[4][4];
#pragma unroll
            for (int i = 0; i < 4; i++)
#pragma unroll
                for (int j = 0; j < 4; j++) acc[i][j] = 0.f;
            const float* qp = QiT + sk * (64 * 32);
            const float* kp = KV + sk * (64 * 32);
#pragma unroll 8
            for (int d = 0; d < 64; d++) {
                float4 av = *reinterpret_cast<const float4*>(qp + d * 32 + si);
                float4 bv = *reinterpret_cast<const float4*>(kp + d * 32 + sj);
                float aa[4] = {av.x, av.y, av.z, av.w};
                float bb[4] = {bv.x, bv.y, bv.z, bv.w};
#pragma unroll
                for (int i = 0; i < 4; i++)
#pragma unroll
                    for (int j = 0; j < 4; j++)
                        acc[i][j] = fmaf(aa[i], bb[j], acc[i][j]);
            }
#pragma unroll
            for (int i = 0; i < 4; i++)
#pragma unroll
                for (int j = 0; j < 4; j++)
                    S[sk * 1056 + (si + i) * 33 + (sj + j)] = acc[i][j];
        }
        __syncthreads();

#pragma unroll 1
        for (int g = 0; g < 3; g++) {
            // V tile for heads 4g..4g+3 into KV (reused buffer): [hs][j][d]
            for (int e = t; e < 2048; e += 256) {
                int hs = e >> 9;
                int r  = (e >> 4) & 31;
                int c4 = (e & 15) << 2;
                float4 vv = *reinterpret_cast<const float4*>(
                    &g_VS[(((b * NH + g * 4 + hs) << 10) + jt + r) * HD + c4]);
                *reinterpret_cast<float4*>(&KV[(hs * 32 + r) * 64 + c4]) = vv;
            }
            // E = 2^(mixed log2-logits) — exp2_fast on fma pipe, no MUFU.
            // No max subtraction needed (|logit| small, see R1-R7 analysis).
            {
                int h = g * 4 + eh;
                float m0 = mixs[h * 4 + 0], m1 = mixs[h * 4 + 1];
                float m2 = mixs[h * 4 + 2], m3 = mixs[h * 4 + 3];
                const float* s0 = S + 0 * 1056 + ei * 33;
                const float* s1 = S + 1 * 1056 + ei * 33;
                const float* s2 = S + 2 * 1056 + ei * 33;
                const float* s3 = S + 3 * 1056 + ei * 33;
                float* erow = E + eh * 1056 + ei * 33;
                float psum = 0.f;
#pragma unroll
                for (int j = ej0; j < ej0 + 16; j++) {
                    float l  = m0 * s0[j] + m1 * s1[j] + m2 * s2[j] + m3 * s3[j];
                    float ev = exp2_fast(l);
                    erow[j] = ev;
                    psum += ev;
                }
                dred[t] = psum;
            }
            __syncthreads();
            if (t < 128)
                den[(g * 4 + (t >> 5)) * 32 + (t & 31)] += dred[t] + dred[t + 128];
            // PV: O[h] += E[h](32x32) @ V[h](32x64)
            {
                float acc[4][8];
#pragma unroll
                for (int i = 0; i < 4; i++)
#pragma unroll
                    for (int d = 0; d < 8; d++) acc[i][d] = 0.f;
                const float* ep = E + ph * 1056 + pi * 33;
                const float* vp = KV + ph * (32 * 64);
#pragma unroll 4
                for (int j = 0; j < 32; j++) {
                    float ee[4] = {ep[j], ep[33 + j], ep[66 + j], ep[99 + j]};
                    float4 v0 = *reinterpret_cast<const float4*>(vp + j * 64 + pd);
                    float4 v1 = *reinterpret_cast<const float4*>(vp + j * 64 + pd + 4);
                    float vv[8] = {v0.x, v0.y, v0.z, v0.w, v1.x, v1.y, v1.z, v1.w};
#pragma unroll
                    for (int i = 0; i < 4; i++)
#pragma unroll
                        for (int d = 0; d < 8; d++)
                            acc[i][d] = fmaf(ee[i], vv[d], acc[i][d]);
                }
                int h = g * 4 + ph;
#pragma unroll
                for (int i = 0; i < 4; i++) {
                    float4* op = reinterpret_cast<float4*>(&O[(h * 32 + pi + i) * 64 + pd]);
                    float4 o0 = op[0], o1 = op[1];
                    o0.x += acc[i][0]; o0.y += acc[i][1];
                    o0.z += acc[i][2]; o0.w += acc[i][3];
                    o1.x += acc[i][4]; o1.y += acc[i][5];
                    o1.z += acc[i][6]; o1.w += acc[i][7];
                    op[0] = o0; op[1] = o1;
                }
            }
            __syncthreads();
        }
    }

    // normalize and write AO[b][n][h*64+d]
    for (int e = t; e < 6144; e += 256) {
        int h  = e >> 9;
        int r  = (e >> 4) & 31;
        int c4 = (e & 15) << 2;
        float inv = 1.f / den[h * 32 + r];
        float4 o = *reinterpret_cast<const float4*>(&O[(h * 32 + r) * 64 + c4]);
        o.x *= inv; o.y *= inv; o.z *= inv; o.w *= inv;
        *reinterpret_cast<float4*>(
            &g_AO[((b << 10) + i0 + r) * DIMS + h * 64 + c4]) = o;
    }
}

// ---------------------------------------------------------------------------
extern "C" void kernel_launch(void* const* d_in, const int* in_sizes, int n_in,
                              void* d_out, int out_size)
{
    const float* x    = (const float*)d_in[0];
    const float* wqkv = (const float*)d_in[1];
    const float* mixl = (const float*)d_in[2];
    const float* wv   = (const float*)d_in[3];
    const float* wpr  = (const float*)d_in[4];
    const float* bpr  = (const float*)d_in[5];
    float* out = (float*)d_out;

    cudaFuncSetAttribute(k_attn, cudaFuncAttributeMaxDynamicSharedMemorySize,
                         SM_TOT * (int)sizeof(float));

    // K1: fused QK + V projections (8192 x 1280)
    k_sgemm<0><<<dim3(64, 10), 256>>>(x, wqkv, wv, nullptr, nullptr);
    // K2: fused flash attention with head mixing
    k_attn<<<dim3(32, 8), 256, SM_TOT * (int)sizeof(float)>>>(mixl);
    // K3: output projection + bias (8192 x 768)
    k_sgemm<1><<<dim3(64, 6), 256>>>(nullptr, wpr, nullptr, bpr, out);
}

// round 12
// speedup vs baseline: 1.0735x; 1.0735x over previous
#include <cuda_runtime.h>
#include <cstdint>

// ---------------------------------------------------------------------------
// FiSHAttention — round 12 (resubmit of R11; broker timeout, never ran).
// R10 result: exp2_fast NEUTRAL (1794us vs 1788) -> K2 is NOT MUFU-bound;
// it is latency/issue-bound (~60% of pipe floors at 8 warps / 1 CTA/SM).
// K1 measured at ~97% of the FFMA roofline -> only tensor cores can help
// the GEMMs. This round: K1/K3 -> mma.sync m16n8k8 tf32 with 3xTF32
// decomposition (fp32-grade accuracy). K2 kept byte-identical to R10 (passed).
// ---------------------------------------------------------------------------

constexpr int BATCH = 8;
constexpr int SEQ   = 1024;
constexpr int DIMS  = 768;
constexpr int NH    = 12;   // local heads
constexpr int NG    = 4;    // global heads
constexpr int HD    = 64;   // head dim
constexpr int TOK   = BATCH * SEQ;          // 8192

// scratch (static device memory — no allocations allowed)
__device__ float g_QS[BATCH * NG * SEQ * HD];   // (b,k,n,d) scaled by 1/8
__device__ float g_KS[BATCH * NG * SEQ * HD];   // (b,k,n,d)
__device__ float g_VS[BATCH * NH * SEQ * HD];   // (b,h,n,d)
__device__ float g_AO[TOK * DIMS];              // (token, h*64+d)

// fast 2^y on the fma/alu pipes (no MUFU). Valid for |y| < ~60.
__device__ __forceinline__ float exp2_fast(float y) {
    float t = y + 12582912.0f;                 // 1.5 * 2^23
    int   n = __float_as_int(t) - 0x4B400000;  // signed integer part
    float f = y - (t - 12582912.0f);           // f in [-0.5, 0.5]
    float p =              0.0013333558f;
    p = fmaf(p, f,         0.0096181291f);
    p = fmaf(p, f,         0.0555041087f);
    p = fmaf(p, f,         0.2402265069f);
    p = fmaf(p, f,         0.6931471806f);
    p = fmaf(p, f,         1.0f);
    return __int_as_float(__float_as_int(p) + (n << 23));
}

// split fp32 into tf32 hi + tf32 lo (3xTF32 decomposition, err ~2^-22)
__device__ __forceinline__ void tf32_split(float a, uint32_t& hi, uint32_t& lo) {
    uint32_t h;
    asm("cvt.rna.tf32.f32 %0, %1;" : "=r"(h) : "f"(a));
    float r = a - __uint_as_float(h);
    uint32_t l;
    asm("cvt.rna.tf32.f32 %0, %1;" : "=r"(l) : "f"(r));
    hi = h; lo = l;
}

__device__ __forceinline__ void mma_tf32(float* c, const uint32_t* a, const uint32_t* b) {
    asm volatile(
        "mma.sync.aligned.m16n8k8.row.col.f32.tf32.tf32.f32 "
        "{%0,%1,%2,%3}, {%4,%5,%6,%7}, {%8,%9}, {%0,%1,%2,%3};"
        : "+f"(c[0]), "+f"(c[1]), "+f"(c[2]), "+f"(c[3])
        : "r"(a[0]), "r"(a[1]), "r"(a[2]), "r"(a[3]), "r"(b[0]), "r"(b[1]));
}

// ---------------------------------------------------------------------------
// Tensor-core GEMM: C[M x NC] = A[M x 768] @ B[NC x 768]^T  (3xTF32)
// BM=BN=128, BK=8, 256 threads = 8 warps (2x4), warp tile 64x32 = 4x4 mmas.
// smem stride 140: conflict-free transposed stores; 2-way max on frag loads.
// EPI==0: A=x, B=cat(w_qkv[0:512], w_v), scatter into QS/KS/VS
// EPI==1: A=g_AO, B=w_proj, C=out + bias
// ---------------------------------------------------------------------------
constexpr int SSTR = 140;

template <int EPI>
__global__ __launch_bounds__(256, 2) void k_mma(
    const float* __restrict__ A,
    const float* __restrict__ B0,
    const float* __restrict__ B1,
    const float* __restrict__ bias,
    float* __restrict__ Cout)
{
    __shared__ float sA[8 * SSTR];
    __shared__ float sB[8 * SSTR];

    const int t    = threadIdx.x;
    const int bm   = blockIdx.x;
    const int bn   = blockIdx.y;
    const int lane = t & 31;
    const int warp = t >> 5;
    const int gid  = lane >> 2;   // 0..7
    const int tid4 = lane & 3;    // 0..3
    const int wm   = warp >> 2;   // 0..1  (row block of 64)
    const int wn   = warp & 3;    // 0..3  (col block of 32)
    const int lr   = t >> 1;      // 0..127 loader row
    const int lc   = (t & 1) << 2;// 0 or 4 loader k-offset

    const float* Ap   = (EPI == 1) ? (const float*)g_AO : A;
    const float* Arow = Ap + (bm * 128 + lr) * DIMS + lc;
    const int    ncol = bn * 128 + lr;
    const float* Brow;
    if (EPI == 0)
        Brow = (ncol < 512) ? (B0 + ncol * DIMS + lc)
                            : (B1 + (ncol - 512) * DIMS + lc);
    else
        Brow = B0 + ncol * DIMS + lc;

    float c[4][4][4];
#pragma unroll
    for (int mt = 0; mt < 4; mt++)
#pragma unroll
        for (int nt = 0; nt < 4; nt++)
#pragma unroll
            for (int e = 0; e < 4; e++) c[mt][nt][e] = 0.f;

    for (int kt = 0; kt < DIMS; kt += 8) {
        float4 av = *reinterpret_cast<const float4*>(Arow + kt);
        float4 bv = *reinterpret_cast<const float4*>(Brow + kt);
        __syncthreads();
        sA[(lc + 0) * SSTR + lr] = av.x; sA[(lc + 1) * SSTR + lr] = av.y;
        sA[(lc + 2) * SSTR + lr] = av.z; sA[(lc + 3) * SSTR + lr] = av.w;
        sB[(lc + 0) * SSTR + lr] = bv.x; sB[(lc + 1) * SSTR + lr] = bv.y;
        sB[(lc + 2) * SSTR + lr] = bv.z; sB[(lc + 3) * SSTR + lr] = bv.w;
        __syncthreads();

        // B fragments (k8 x n8, col-major): b0 (k=tid4, n=cb), b1 (k=tid4+4)
        uint32_t bh[4][2], bl[4][2];
#pragma unroll
        for (int nt = 0; nt < 4; nt++) {
            int cb = wn * 32 + nt * 8 + gid;
            tf32_split(sB[ tid4      * SSTR + cb], bh[nt][0], bl[nt][0]);
            tf32_split(sB[(tid4 + 4) * SSTR + cb], bh[nt][1], bl[nt][1]);
        }
#pragma unroll
        for (int mt = 0; mt < 4; mt++) {
            int rb = wm * 64 + mt * 16 + gid;
            uint32_t ah[4], al[4];
            tf32_split(sA[ tid4      * SSTR + rb    ], ah[0], al[0]);
            tf32_split(sA[ tid4      * SSTR + rb + 8], ah[1], al[1]);
            tf32_split(sA[(tid4 + 4) * SSTR + rb    ], ah[2], al[2]);
            tf32_split(sA[(tid4 + 4) * SSTR + rb + 8], ah[3], al[3]);
#pragma unroll
            for (int nt = 0; nt < 4; nt++) {
                mma_tf32(c[mt][nt], al, bh[nt]);   // lo*hi
                mma_tf32(c[mt][nt], ah, bl[nt]);   // hi*lo
                mma_tf32(c[mt][nt], ah, bh[nt]);   // hi*hi
            }
        }
    }

    // epilogue: thread owns rows {m0, m0+8}, col pair {n0, n0+1} per (mt,nt)
#pragma unroll
    for (int mt = 0; mt < 4; mt++)
#pragma unroll
        for (int nt = 0; nt < 4; nt++) {
            int m0 = bm * 128 + wm * 64 + mt * 16 + gid;
            int n0 = bn * 128 + wn * 32 + nt * 8 + tid4 * 2;
#pragma unroll
            for (int rs = 0; rs < 2; rs++) {
                int   m  = m0 + rs * 8;
                float v0 = c[mt][nt][rs * 2 + 0];
                float v1 = c[mt][nt][rs * 2 + 1];
                int bidx = m >> 10;
                int n    = m & 1023;
                if (EPI == 0) {
                    int d = n0 & 63;  // pair stays inside one 64-col segment
                    if (n0 < 256) {
                        int k = n0 >> 6;
                        *reinterpret_cast<float2*>(
                            &g_QS[(((bidx * NG + k) << 10) + n) * HD + d]) =
                            make_float2(v0 * 0.125f, v1 * 0.125f);
                    } else if (n0 < 512) {
                        int k = (n0 - 256) >> 6;
                        *reinterpret_cast<float2*>(
                            &g_KS[(((bidx * NG + k) << 10) + n) * HD + d]) =
                            make_float2(v0, v1);
                    } else {
                        int h = (n0 - 512) >> 6;
                        *reinterpret_cast<float2*>(
                            &g_VS[(((bidx * NH + h) << 10) + n) * HD + d]) =
                            make_float2(v0, v1);
                    }
                } else {
                    *reinterpret_cast<float2*>(&Cout[m * DIMS + n0]) =
                        make_float2(v0 + bias[n0], v1 + bias[n0 + 1]);
                }
            }
        }
}

// ---------------------------------------------------------------------------
// Fused flash attention (unchanged from R10 — passed, rel_err 3.8e-7).
// grid = (32 i-tiles, 8 batches), 256 threads, TM=TN=32.
// ---------------------------------------------------------------------------
constexpr int SM_QIT  = 0;
constexpr int SM_KV   = SM_QIT + 4 * 64 * 32;      // 8192
constexpr int SM_S    = SM_KV + 4 * 64 * 32;       // 16384
constexpr int SM_E    = SM_S + 4 * 32 * 33;        // 20608
constexpr int SM_O    = SM_E + 4 * 32 * 33;        // 24832
constexpr int SM_DEN  = SM_O + 12 * 32 * 64;       // 49408
constexpr int SM_DRED = SM_DEN + 12 * 32;          // 49792
constexpr int SM_MIX  = SM_DRED + 256;             // 50048
constexpr int SM_TOT  = SM_MIX + 48;               // 50096 floats = 200384 B

__global__ __launch_bounds__(256, 1) void k_attn(const float* __restrict__ mix_logits)
{
    extern __shared__ float sm[];
    float* QiT  = sm + SM_QIT;
    float* KV   = sm + SM_KV;
    float* S    = sm + SM_S;
    float* E    = sm + SM_E;
    float* O    = sm + SM_O;
    float* den  = sm + SM_DEN;
    float* dred = sm + SM_DRED;
    float* mixs = sm + SM_MIX;

    const int t  = threadIdx.x;
    const int b  = blockIdx.y;
    const int i0 = blockIdx.x * 32;

    if (t < NH) {
        float m0 = mix_logits[t * 4 + 0], m1 = mix_logits[t * 4 + 1];
        float m2 = mix_logits[t * 4 + 2], m3 = mix_logits[t * 4 + 3];
        float mx = fmaxf(fmaxf(m0, m1), fmaxf(m2, m3));
        float e0 = __expf(m0 - mx), e1 = __expf(m1 - mx);
        float e2 = __expf(m2 - mx), e3 = __expf(m3 - mx);
        float inv = 1.4426950408889634f / (e0 + e1 + e2 + e3);  // log2e / sum
        mixs[t * 4 + 0] = e0 * inv; mixs[t * 4 + 1] = e1 * inv;
        mixs[t * 4 + 2] = e2 * inv; mixs[t * 4 + 3] = e3 * inv;
    }
    for (int e = t; e < 12 * 32 * 64 / 4; e += 256)
        reinterpret_cast<float4*>(O)[e] = make_float4(0.f, 0.f, 0.f, 0.f);
    for (int e = t; e < 12 * 32; e += 256) den[e] = 0.f;

    for (int e = t; e < 2048; e += 256) {
        int k  = e >> 9;
        int r  = (e >> 4) & 31;
        int c4 = (e & 15) << 2;
        float4 q = *reinterpret_cast<const float4*>(
            &g_QS[(((b * NG + k) << 10) + i0 + r) * HD + c4]);
        QiT[(k * 64 + c4 + 0) * 32 + r] = q.x;
        QiT[(k * 64 + c4 + 1) * 32 + r] = q.y;
        QiT[(k * 64 + c4 + 2) * 32 + r] = q.z;
        QiT[(k * 64 + c4 + 3) * 32 + r] = q.w;
    }
    __syncthreads();

    const int sk  = t >> 6;
    const int s64 = t & 63;
    const int si  = (s64 >> 3) << 2;
    const int sj  = (s64 & 7) << 2;

    const int eh  = (t & 127) >> 5;
    const int ei  = t & 31;
    const int ej0 = (t >> 7) << 4;

    const int ph  = t >> 6;
    const int p64 = t & 63;
    const int pi  = (p64 >> 3) << 2;
    const int pd  = (p64 & 7) << 3;

    for (int jt = 0; jt < SEQ; jt += 32) {
        for (int e = t; e < 2048; e += 256) {
            int k  = e >> 9;
            int r  = (e >> 4) & 31;
            int c4 = (e & 15) << 2;
            float4 kv = *reinterpret_cast<const float4*>(
                &g_KS[(((b * NG + k) << 10) + jt + r) * HD + c4]);
            KV[(k * 64 + c4 + 0) * 32 + r] = kv.x;
            KV[(k * 64 + c4 + 1) * 32 + r] = kv.y;
            KV[(k * 64 + c4 + 2) * 32 + r] = kv.z;
            KV[(k * 64 + c4 + 3) * 32 + r] = kv.w;
        }
        __syncthreads();

        {
            float acc[4][4];
#pragma unroll
            for (int i = 0; i < 4; i++)
#pragma unroll
                for (int j = 0; j < 4; j++) acc[i][j] = 0.f;
            const float* qp = QiT + sk * (64 * 32);
            const float* kp = KV + sk * (64 * 32);
#pragma unroll 8
            for (int d = 0; d < 64; d++) {
                float4 av = *reinterpret_cast<const float4*>(qp + d * 32 + si);
                float4 bv = *reinterpret_cast<const float4*>(kp + d * 32 + sj);
                float aa[4] = {av.x, av.y, av.z, av.w};
                float bb[4] = {bv.x, bv.y, bv.z, bv.w};
#pragma unroll
                for (int i = 0; i < 4; i++)
#pragma unroll
                    for (int j = 0; j < 4; j++)
                        acc[i][j] = fmaf(aa[i], bb[j], acc[i][j]);
            }
#pragma unroll
            for (int i = 0; i < 4; i++)
#pragma unroll
                for (int j = 0; j < 4; j++)
                    S[sk * 1056 + (si + i) * 33 + (sj + j)] = acc[i][j];
        }
        __syncthreads();

#pragma unroll 1
        for (int g = 0; g < 3; g++) {
            for (int e = t; e < 2048; e += 256) {
                int hs = e >> 9;
                int r  = (e >> 4) & 31;
                int c4 = (e & 15) << 2;
                float4 vv = *reinterpret_cast<const float4*>(
                    &g_VS[(((b * NH + g * 4 + hs) << 10) + jt + r) * HD + c4]);
                *reinterpret_cast<float4*>(&KV[(hs * 32 + r) * 64 + c4]) = vv;
            }
            {
                int h = g * 4 + eh;
                float m0 = mixs[h * 4 + 0], m1 = mixs[h * 4 + 1];
                float m2 = mixs[h * 4 + 2], m3 = mixs[h * 4 + 3];
                const float* s0 = S + 0 * 1056 + ei * 33;
                const float* s1 = S + 1 * 1056 + ei * 33;
                const float* s2 = S + 2 * 1056 + ei * 33;
                const float* s3 = S + 3 * 1056 + ei * 33;
                float* erow = E + eh * 1056 + ei * 33;
                float psum = 0.f;
#pragma unroll
                for (int j = ej0; j < ej0 + 16; j++) {
                    float l  = m0 * s0[j] + m1 * s1[j] + m2 * s2[j] + m3 * s3[j];
                    float ev = exp2_fast(l);
                    erow[j] = ev;
                    psum += ev;
                }
                dred[t] = psum;
            }
            __syncthreads();
            if (t < 128)
                den[(g * 4 + (t >> 5)) * 32 + (t & 31)] += dred[t] + dred[t + 128];
            {
                float acc[4][8];
#pragma unroll
                for (int i = 0; i < 4; i++)
#pragma unroll
                    for (int d = 0; d < 8; d++) acc[i][d] = 0.f;
                const float* ep = E + ph * 1056 + pi * 33;
                const float* vp = KV + ph * (32 * 64);
#pragma unroll 4
                for (int j = 0; j < 32; j++) {
                    float ee[4] = {ep[j], ep[33 + j], ep[66 + j], ep[99 + j]};
                    float4 v0 = *reinterpret_cast<const float4*>(vp + j * 64 + pd);
                    float4 v1 = *reinterpret_cast<const float4*>(vp + j * 64 + pd + 4);
                    float vv[8] = {v0.x, v0.y, v0.z, v0.w, v1.x, v1.y, v1.z, v1.w};
#pragma unroll
                    for (int i = 0; i < 4; i++)
#pragma unroll
                        for (int d = 0; d < 8; d++)
                            acc[i][d] = fmaf(ee[i], vv[d], acc[i][d]);
                }
                int h = g * 4 + ph;
#pragma unroll
                for (int i = 0; i < 4; i++) {
                    float4* op = reinterpret_cast<float4*>(&O[(h * 32 + pi + i) * 64 + pd]);
                    float4 o0 = op[0], o1 = op[1];
                    o0.x += acc[i][0]; o0.y += acc[i][1];
                    o0.z += acc[i][2]; o0.w += acc[i][3];
                    o1.x += acc[i][4]; o1.y += acc[i][5];
                    o1.z += acc[i][6]; o1.w += acc[i][7];
                    op[0] = o0; op[1] = o1;
                }
            }
            __syncthreads();
        }
    }

    for (int e = t; e < 6144; e += 256) {
        int h  = e >> 9;
        int r  = (e >> 4) & 31;
        int c4 = (e & 15) << 2;
        float inv = 1.f / den[h * 32 + r];
        float4 o = *reinterpret_cast<const float4*>(&O[(h * 32 + r) * 64 + c4]);
        o.x *= inv; o.y *= inv; o.z *= inv; o.w *= inv;
        *reinterpret_cast<float4*>(
            &g_AO[((b << 10) + i0 + r) * DIMS + h * 64 + c4]) = o;
    }
}

// ---------------------------------------------------------------------------
extern "C" void kernel_launch(void* const* d_in, const int* in_sizes, int n_in,
                              void* d_out, int out_size)
{
    const float* x    = (const float*)d_in[0];
    const float* wqkv = (const float*)d_in[1];
    const float* mixl = (const float*)d_in[2];
    const float* wv   = (const float*)d_in[3];
    const float* wpr  = (const float*)d_in[4];
    const float* bpr  = (const float*)d_in[5];
    float* out = (float*)d_out;

    cudaFuncSetAttribute(k_attn, cudaFuncAttributeMaxDynamicSharedMemorySize,
                         SM_TOT * (int)sizeof(float));

    // K1: fused QK + V projections (8192 x 1280), 3xTF32 tensor cores
    k_mma<0><<<dim3(64, 10), 256>>>(x, wqkv, wv, nullptr, nullptr);
    // K2: fused flash attention with head mixing
    k_attn<<<dim3(32, 8), 256, SM_TOT * (int)sizeof(float)>>>(mixl);
    // K3: output projection + bias (8192 x 768), 3xTF32 tensor cores
    k_mma<1><<<dim3(64, 6), 256>>>(nullptr, wpr, nullptr, bpr, out);
}

// round 13
// speedup vs baseline: 1.1361x; 1.0583x over previous
#include <cuda_runtime.h>
#include <cstdint>

// ---------------------------------------------------------------------------
// FiSHAttention — round 13.
// R12: 1671us (K1 338us via 3xTF32 MMA, tensor=46.6%). K2 ~1130us = 67% and
// is scalar-FMA/issue-bound (R10). This round: K2's S=QK^T and PV ported to
// the SAME hardware-validated m16n8k8 3xTF32 path. PV computed as
// O^T = V^T @ E^T so V stays natural [j][d] in smem (no transpose stores).
// Strides 68/72/36/33 give conflict-free fragment loads (bank algebra in
// comments). Scalar mix+exp2_fast phase kept between the two MMA stages.
// K1/K3 unchanged from R12 (banked win).
// ---------------------------------------------------------------------------

constexpr int BATCH = 8;
constexpr int SEQ   = 1024;
constexpr int DIMS  = 768;
constexpr int NH    = 12;   // local heads
constexpr int NG    = 4;    // global heads
constexpr int HD    = 64;   // head dim
constexpr int TOK   = BATCH * SEQ;          // 8192

__device__ float g_QS[BATCH * NG * SEQ * HD];   // (b,k,n,d) scaled by 1/8
__device__ float g_KS[BATCH * NG * SEQ * HD];   // (b,k,n,d)
__device__ float g_VS[BATCH * NH * SEQ * HD];   // (b,h,n,d)
__device__ float g_AO[TOK * DIMS];              // (token, h*64+d)

// fast 2^y on the fma/alu pipes (no MUFU). Valid for |y| < ~60.
__device__ __forceinline__ float exp2_fast(float y) {
    float t = y + 12582912.0f;                 // 1.5 * 2^23
    int   n = __float_as_int(t) - 0x4B400000;  // signed integer part
    float f = y - (t - 12582912.0f);           // f in [-0.5, 0.5]
    float p =              0.0013333558f;
    p = fmaf(p, f,         0.0096181291f);
    p = fmaf(p, f,         0.0555041087f);
    p = fmaf(p, f,         0.2402265069f);
    p = fmaf(p, f,         0.6931471806f);
    p = fmaf(p, f,         1.0f);
    return __int_as_float(__float_as_int(p) + (n << 23));
}

// split fp32 into tf32 hi + tf32 lo (3xTF32 decomposition, err ~2^-22)
__device__ __forceinline__ void tf32_split(float a, uint32_t& hi, uint32_t& lo) {
    uint32_t h;
    asm("cvt.rna.tf32.f32 %0, %1;" : "=r"(h) : "f"(a));
    float r = a - __uint_as_float(h);
    uint32_t l;
    asm("cvt.rna.tf32.f32 %0, %1;" : "=r"(l) : "f"(r));
    hi = h; lo = l;
}

__device__ __forceinline__ void mma_tf32(float* c, const uint32_t* a, const uint32_t* b) {
    asm volatile(
        "mma.sync.aligned.m16n8k8.row.col.f32.tf32.tf32.f32 "
        "{%0,%1,%2,%3}, {%4,%5,%6,%7}, {%8,%9}, {%0,%1,%2,%3};"
        : "+f"(c[0]), "+f"(c[1]), "+f"(c[2]), "+f"(c[3])
        : "r"(a[0]), "r"(a[1]), "r"(a[2]), "r"(a[3]), "r"(b[0]), "r"(b[1]));
}

// ---------------------------------------------------------------------------
// Tensor-core GEMM (unchanged from R12 — passed, 338us for EPI=0)
// ---------------------------------------------------------------------------
constexpr int SSTR = 140;

template <int EPI>
__global__ __launch_bounds__(256, 2) void k_mma(
    const float* __restrict__ A,
    const float* __restrict__ B0,
    const float* __restrict__ B1,
    const float* __restrict__ bias,
    float* __restrict__ Cout)
{
    __shared__ float sA[8 * SSTR];
    __shared__ float sB[8 * SSTR];

    const int t    = threadIdx.x;
    const int bm   = blockIdx.x;
    const int bn   = blockIdx.y;
    const int lane = t & 31;
    const int warp = t >> 5;
    const int gid  = lane >> 2;
    const int tid4 = lane & 3;
    const int wm   = warp >> 2;
    const int wn   = warp & 3;
    const int lr   = t >> 1;
    const int lc   = (t & 1) << 2;

    const float* Ap   = (EPI == 1) ? (const float*)g_AO : A;
    const float* Arow = Ap + (bm * 128 + lr) * DIMS + lc;
    const int    ncol = bn * 128 + lr;
    const float* Brow;
    if (EPI == 0)
        Brow = (ncol < 512) ? (B0 + ncol * DIMS + lc)
                            : (B1 + (ncol - 512) * DIMS + lc);
    else
        Brow = B0 + ncol * DIMS + lc;

    float c[4][4][4];
#pragma unroll
    for (int mt = 0; mt < 4; mt++)
#pragma unroll
        for (int nt = 0; nt < 4; nt++)
#pragma unroll
            for (int e = 0; e < 4; e++) c[mt][nt][e] = 0.f;

    for (int kt = 0; kt < DIMS; kt += 8) {
        float4 av = *reinterpret_cast<const float4*>(Arow + kt);
        float4 bv = *reinterpret_cast<const float4*>(Brow + kt);
        __syncthreads();
        sA[(lc + 0) * SSTR + lr] = av.x; sA[(lc + 1) * SSTR + lr] = av.y;
        sA[(lc + 2) * SSTR + lr] = av.z; sA[(lc + 3) * SSTR + lr] = av.w;
        sB[(lc + 0) * SSTR + lr] = bv.x; sB[(lc + 1) * SSTR + lr] = bv.y;
        sB[(lc + 2) * SSTR + lr] = bv.z; sB[(lc + 3) * SSTR + lr] = bv.w;
        __syncthreads();

        uint32_t bh[4][2], bl[4][2];
#pragma unroll
        for (int nt = 0; nt < 4; nt++) {
            int cb = wn * 32 + nt * 8 + gid;
            tf32_split(sB[ tid4      * SSTR + cb], bh[nt][0], bl[nt][0]);
            tf32_split(sB[(tid4 + 4) * SSTR + cb], bh[nt][1], bl[nt][1]);
        }
#pragma unroll
        for (int mt = 0; mt < 4; mt++) {
            int rb = wm * 64 + mt * 16 + gid;
            uint32_t ah[4], al[4];
            tf32_split(sA[ tid4      * SSTR + rb    ], ah[0], al[0]);
            tf32_split(sA[ tid4      * SSTR + rb + 8], ah[1], al[1]);
            tf32_split(sA[(tid4 + 4) * SSTR + rb    ], ah[2], al[2]);
            tf32_split(sA[(tid4 + 4) * SSTR + rb + 8], ah[3], al[3]);
#pragma unroll
            for (int nt = 0; nt < 4; nt++) {
                mma_tf32(c[mt][nt], al, bh[nt]);
                mma_tf32(c[mt][nt], ah, bl[nt]);
                mma_tf32(c[mt][nt], ah, bh[nt]);
            }
        }
    }

#pragma unroll
    for (int mt = 0; mt < 4; mt++)
#pragma unroll
        for (int nt = 0; nt < 4; nt++) {
            int m0 = bm * 128 + wm * 64 + mt * 16 + gid;
            int n0 = bn * 128 + wn * 32 + nt * 8 + tid4 * 2;
#pragma unroll
            for (int rs = 0; rs < 2; rs++) {
                int   m  = m0 + rs * 8;
                float v0 = c[mt][nt][rs * 2 + 0];
                float v1 = c[mt][nt][rs * 2 + 1];
                int bidx = m >> 10;
                int n    = m & 1023;
                if (EPI == 0) {
                    int d = n0 & 63;
                    if (n0 < 256) {
                        int k = n0 >> 6;
                        *reinterpret_cast<float2*>(
                            &g_QS[(((bidx * NG + k) << 10) + n) * HD + d]) =
                            make_float2(v0 * 0.125f, v1 * 0.125f);
                    } else if (n0 < 512) {
                        int k = (n0 - 256) >> 6;
                        *reinterpret_cast<float2*>(
                            &g_KS[(((bidx * NG + k) << 10) + n) * HD + d]) =
                            make_float2(v0, v1);
                    } else {
                        int h = (n0 - 512) >> 6;
                        *reinterpret_cast<float2*>(
                            &g_VS[(((bidx * NH + h) << 10) + n) * HD + d]) =
                            make_float2(v0, v1);
                    }
                } else {
                    *reinterpret_cast<float2*>(&Cout[m * DIMS + n0]) =
                        make_float2(v0 + bias[n0], v1 + bias[n0 + 1]);
                }
            }
        }
}

// ---------------------------------------------------------------------------
// Fused flash attention, tensor-core edition.
// grid = (32 i-tiles, 8 batches), 256 threads = 8 warps.
// Warp w: head hw=w>>1, half=w&1 (16-col slice) for both S and PV.
// Layouts (floats): Qs/Ks [row][d|j] str 68 | Vs [j][d] str 72 |
//                   S/E [i][j] str 36 | O^T [d][i] str 33.
// Fragment bank algebra (all distinct mod 32):
//   Q/K frags: 4*gid+tid4 ; V frags: 8*tid4+gid ; E frags: 4*gid+tid4.
// PV computes O^T = V^T(d,j) @ E^T(j,i)  ==  (E@V)^T — avoids V transpose.
// ---------------------------------------------------------------------------
constexpr int QSTR = 68;
constexpr int VSTR = 72;
constexpr int SST  = 36;
constexpr int OSTR = 33;

constexpr int SM2_Q    = 0;                          // 4*32*68  = 8704
constexpr int SM2_KV   = SM2_Q   + 4 * 32 * QSTR;    // 8704 ; sz 4*32*72 = 9216
constexpr int SM2_S    = SM2_KV  + 4 * 32 * VSTR;    // 17920; sz 4608
constexpr int SM2_E    = SM2_S   + 4 * 32 * SST;     // 22528; sz 4608
constexpr int SM2_OT   = SM2_E   + 4 * 32 * SST;     // 27136; sz 12*64*33 = 25344
constexpr int SM2_DEN  = SM2_OT  + 12 * 64 * OSTR;   // 52480; sz 384
constexpr int SM2_DRED = SM2_DEN + 384;              // 52864; sz 256
constexpr int SM2_MIX  = SM2_DRED + 256;             // 53120; sz 48
constexpr int SM2_TOT  = SM2_MIX + 48;               // 53168 floats = 212672 B

__global__ __launch_bounds__(256, 1) void k_attn(const float* __restrict__ mix_logits)
{
    extern __shared__ float sm[];
    float* Qs   = sm + SM2_Q;
    float* KVs  = sm + SM2_KV;
    float* Ss   = sm + SM2_S;
    float* Es   = sm + SM2_E;
    float* OT   = sm + SM2_OT;
    float* den  = sm + SM2_DEN;
    float* dred = sm + SM2_DRED;
    float* mixs = sm + SM2_MIX;

    const int t    = threadIdx.x;
    const int b    = blockIdx.y;
    const int i0   = blockIdx.x * 32;
    const int lane = t & 31;
    const int warp = t >> 5;
    const int gid  = lane >> 2;
    const int tid4 = lane & 3;
    const int hw   = warp >> 1;   // head 0..3 (S head / PV head-in-group)
    const int half = warp & 1;    // 16-wide column slice

    // head-mix softmax, pre-scaled by log2(e) for the base-2 E phase
    if (t < NH) {
        float m0 = mix_logits[t * 4 + 0], m1 = mix_logits[t * 4 + 1];
        float m2 = mix_logits[t * 4 + 2], m3 = mix_logits[t * 4 + 3];
        float mx = fmaxf(fmaxf(m0, m1), fmaxf(m2, m3));
        float e0 = __expf(m0 - mx), e1 = __expf(m1 - mx);
        float e2 = __expf(m2 - mx), e3 = __expf(m3 - mx);
        float inv = 1.4426950408889634f / (e0 + e1 + e2 + e3);
        mixs[t * 4 + 0] = e0 * inv; mixs[t * 4 + 1] = e1 * inv;
        mixs[t * 4 + 2] = e2 * inv; mixs[t * 4 + 3] = e3 * inv;
    }
    for (int e = t; e < 12 * 64 * OSTR; e += 256) OT[e] = 0.f;  // 25344 = 99*256
    for (int e = t; e < 12 * 32; e += 256) den[e] = 0.f;

    // Q tile, natural [i][d] stride 68
    for (int e = t; e < 2048; e += 256) {
        int k = e >> 9, r = (e >> 4) & 31, c4 = (e & 15) << 2;
        float4 q = *reinterpret_cast<const float4*>(
            &g_QS[(((b * NG + k) << 10) + i0 + r) * HD + c4]);
        *reinterpret_cast<float4*>(&Qs[k * (32 * QSTR) + r * QSTR + c4]) = q;
    }
    __syncthreads();

    const int eh  = (t & 127) >> 5;   // E phase: head-in-group
    const int ei  = t & 31;           // E phase: row
    const int ej0 = (t >> 7) << 4;    // E phase: j half

    for (int jt = 0; jt < SEQ; jt += 32) {
        // K tile, natural [j][d] stride 68 (into KVs)
        for (int e = t; e < 2048; e += 256) {
            int k = e >> 9, r = (e >> 4) & 31, c4 = (e & 15) << 2;
            float4 kv = *reinterpret_cast<const float4*>(
                &g_KS[(((b * NG + k) << 10) + jt + r) * HD + c4]);
            *reinterpret_cast<float4*>(&KVs[k * (32 * QSTR) + r * QSTR + c4]) = kv;
        }
        __syncthreads();

        // ---- S[hw] = Q @ K^T (32x32, this warp: 16-col half), 3xTF32 ----
        {
            float cs[2][2][4];
#pragma unroll
            for (int mt = 0; mt < 2; mt++)
#pragma unroll
                for (int nt = 0; nt < 2; nt++)
#pragma unroll
                    for (int e = 0; e < 4; e++) cs[mt][nt][e] = 0.f;
            const float* qb = Qs  + hw * (32 * QSTR);
            const float* kb = KVs + hw * (32 * QSTR);
#pragma unroll
            for (int ks = 0; ks < 8; ks++) {
                int ko = ks * 8;
                uint32_t bh[2][2], bl[2][2];
#pragma unroll
                for (int nt = 0; nt < 2; nt++) {
                    int n = half * 16 + nt * 8 + gid;
                    tf32_split(kb[n * QSTR + ko + tid4    ], bh[nt][0], bl[nt][0]);
                    tf32_split(kb[n * QSTR + ko + tid4 + 4], bh[nt][1], bl[nt][1]);
                }
#pragma unroll
                for (int mt = 0; mt < 2; mt++) {
                    int rw = mt * 16 + gid;
                    uint32_t ah[4], al[4];
                    tf32_split(qb[ rw      * QSTR + ko + tid4    ], ah[0], al[0]);
                    tf32_split(qb[(rw + 8) * QSTR + ko + tid4    ], ah[1], al[1]);
                    tf32_split(qb[ rw      * QSTR + ko + tid4 + 4], ah[2], al[2]);
                    tf32_split(qb[(rw + 8) * QSTR + ko + tid4 + 4], ah[3], al[3]);
#pragma unroll
                    for (int nt = 0; nt < 2; nt++) {
                        mma_tf32(cs[mt][nt], al, bh[nt]);
                        mma_tf32(cs[mt][nt], ah, bl[nt]);
                        mma_tf32(cs[mt][nt], ah, bh[nt]);
                    }
                }
            }
            float* sb = Ss + hw * (32 * SST);
#pragma unroll
            for (int mt = 0; mt < 2; mt++)
#pragma unroll
                for (int nt = 0; nt < 2; nt++) {
                    int rw = mt * 16 + gid;
                    int cl = half * 16 + nt * 8 + 2 * tid4;
                    sb[ rw      * SST + cl    ] = cs[mt][nt][0];
                    sb[ rw      * SST + cl + 1] = cs[mt][nt][1];
                    sb[(rw + 8) * SST + cl    ] = cs[mt][nt][2];
                    sb[(rw + 8) * SST + cl + 1] = cs[mt][nt][3];
                }
        }
        __syncthreads();

#pragma unroll 1
        for (int g = 0; g < 3; g++) {
            // V tile for heads 4g..4g+3, natural [j][d] stride 72 (reuses KVs)
            for (int e = t; e < 2048; e += 256) {
                int hs = e >> 9, r = (e >> 4) & 31, c4 = (e & 15) << 2;
                float4 vv = *reinterpret_cast<const float4*>(
                    &g_VS[(((b * NH + g * 4 + hs) << 10) + jt + r) * HD + c4]);
                *reinterpret_cast<float4*>(&KVs[hs * (32 * VSTR) + r * VSTR + c4]) = vv;
            }
            // E = 2^(mixed log2-logits), scalar (no max-sub; logits tiny)
            {
                int h = g * 4 + eh;
                float m0 = mixs[h * 4 + 0], m1 = mixs[h * 4 + 1];
                float m2 = mixs[h * 4 + 2], m3 = mixs[h * 4 + 3];
                const float* s0 = Ss + 0 * (32 * SST) + ei * SST;
                const float* s1 = Ss + 1 * (32 * SST) + ei * SST;
                const float* s2 = Ss + 2 * (32 * SST) + ei * SST;
                const float* s3 = Ss + 3 * (32 * SST) + ei * SST;
                float* erow = Es + eh * (32 * SST) + ei * SST;
                float psum = 0.f;
#pragma unroll
                for (int j = ej0; j < ej0 + 16; j++) {
                    float l  = m0 * s0[j] + m1 * s1[j] + m2 * s2[j] + m3 * s3[j];
                    float ev = exp2_fast(l);
                    erow[j] = ev;
                    psum += ev;
                }
                dred[t] = psum;
            }
            __syncthreads();
            if (t < 128)
                den[(g * 4 + (t >> 5)) * 32 + (t & 31)] += dred[t] + dred[t + 128];
            // ---- PV: O^T[h] += V^T @ E^T (64x32, this warp: 16 i-cols) ----
            {
                float cp[4][2][4];
#pragma unroll
                for (int mt = 0; mt < 4; mt++)
#pragma unroll
                    for (int nt = 0; nt < 2; nt++)
#pragma unroll
                        for (int e = 0; e < 4; e++) cp[mt][nt][e] = 0.f;
                const float* vb = KVs + hw * (32 * VSTR);
                const float* eb = Es  + hw * (32 * SST);
#pragma unroll
                for (int ks = 0; ks < 4; ks++) {
                    int jo = ks * 8;
                    uint32_t bh[2][2], bl[2][2];
#pragma unroll
                    for (int nt = 0; nt < 2; nt++) {
                        int ic = half * 16 + nt * 8 + gid;
                        tf32_split(eb[ic * SST + jo + tid4    ], bh[nt][0], bl[nt][0]);
                        tf32_split(eb[ic * SST + jo + tid4 + 4], bh[nt][1], bl[nt][1]);
                    }
#pragma unroll
                    for (int mt = 0; mt < 4; mt++) {
                        int dr = mt * 16 + gid;
                        uint32_t ah[4], al[4];
                        tf32_split(vb[(jo + tid4    ) * VSTR + dr    ], ah[0], al[0]);
                        tf32_split(vb[(jo + tid4    ) * VSTR + dr + 8], ah[1], al[1]);
                        tf32_split(vb[(jo + tid4 + 4) * VSTR + dr    ], ah[2], al[2]);
                        tf32_split(vb[(jo + tid4 + 4) * VSTR + dr + 8], ah[3], al[3]);
#pragma unroll
                        for (int nt = 0; nt < 2; nt++) {
                            mma_tf32(cp[mt][nt], al, bh[nt]);
                            mma_tf32(cp[mt][nt], ah, bl[nt]);
                            mma_tf32(cp[mt][nt], ah, bh[nt]);
                        }
                    }
                }
                float* ob = OT + (g * 4 + hw) * (64 * OSTR);
#pragma unroll
                for (int mt = 0; mt < 4; mt++)
#pragma unroll
                    for (int nt = 0; nt < 2; nt++) {
                        int dr = mt * 16 + gid;
                        int ic = half * 16 + nt * 8 + 2 * tid4;
                        ob[ dr      * OSTR + ic    ] += cp[mt][nt][0];
                        ob[ dr      * OSTR + ic + 1] += cp[mt][nt][1];
                        ob[(dr + 8) * OSTR + ic    ] += cp[mt][nt][2];
                        ob[(dr + 8) * OSTR + ic + 1] += cp[mt][nt][3];
                    }
            }
            __syncthreads();
        }
    }

    // normalize O^T and write AO[b][n][h*64+d]
    for (int e = t; e < 6144; e += 256) {
        int h  = e >> 9;
        int r  = (e >> 4) & 31;
        int c4 = (e & 15) << 2;
        float inv = 1.f / den[h * 32 + r];
        const float* ob = OT + h * (64 * OSTR);
        float4 o;
        o.x = ob[(c4 + 0) * OSTR + r] * inv;
        o.y = ob[(c4 + 1) * OSTR + r] * inv;
        o.z = ob[(c4 + 2) * OSTR + r] * inv;
        o.w = ob[(c4 + 3) * OSTR + r] * inv;
        *reinterpret_cast<float4*>(
            &g_AO[((b << 10) + i0 + r) * DIMS + h * 64 + c4]) = o;
    }
}

// ---------------------------------------------------------------------------
extern "C" void kernel_launch(void* const* d_in, const int* in_sizes, int n_in,
                              void* d_out, int out_size)
{
    const float* x    = (const float*)d_in[0];
    const float* wqkv = (const float*)d_in[1];
    const float* mixl = (const float*)d_in[2];
    const float* wv   = (const float*)d_in[3];
    const float* wpr  = (const float*)d_in[4];
    const float* bpr  = (const float*)d_in[5];
    float* out = (float*)d_out;

    cudaFuncSetAttribute(k_attn, cudaFuncAttributeMaxDynamicSharedMemorySize,
                         SM2_TOT * (int)sizeof(float));

    // K1: fused QK + V projections, 3xTF32 tensor cores
    k_mma<0><<<dim3(64, 10), 256>>>(x, wqkv, wv, nullptr, nullptr);
    // K2: fused flash attention, S and PV on tensor cores (3xTF32)
    k_attn<<<dim3(32, 8), 256, SM2_TOT * (int)sizeof(float)>>>(mixl);
    // K3: output projection + bias, 3xTF32 tensor cores
    k_mma<1><<<dim3(64, 6), 256>>>(nullptr, wpr, nullptr, bpr, out);
}

// round 16
// speedup vs baseline: 1.5666x; 1.3789x over previous
#include <cuda_runtime.h>
#include <cstdint>

// ---------------------------------------------------------------------------
// FiSHAttention — round 16 (resubmit of R15; broker timeout, never ran).
// R15 fixed the R14 E-phase j-coverage bug (8 j per thread, full [0,32)).
// Design (R13 post-mortem): both kernels MMA-ISSUE-bound; K2 uses bf16
// m16n8k16 3-term (hi/lo split, err ~2^-16) with operands pre-packed once
// per tile into bf16x2 hi/lo smem; i-tile=16, O in registers, V stored
// transposed by K1 (g_VST[b,h,d,n]). K1/K3 keep proven 3xTF32 (R12/R13).
// Fragment maps re-verified against PTX m16n8k16 spec this round.
// ---------------------------------------------------------------------------

constexpr int BATCH = 8;
constexpr int SEQ   = 1024;
constexpr int DIMS  = 768;
constexpr int NH    = 12;
constexpr int NG    = 4;
constexpr int HD    = 64;
constexpr int TOK   = BATCH * SEQ;

__device__ float g_QS[BATCH * NG * SEQ * HD];    // (b,k,n,d) scaled 1/8
__device__ float g_KS[BATCH * NG * SEQ * HD];    // (b,k,n,d)
__device__ float g_VST[BATCH * NH * HD * SEQ];   // (b,h,d,n)  TRANSPOSED
__device__ float g_AO[TOK * DIMS];               // (token, h*64+d)

// fast 2^y on fma/alu pipes (no MUFU), |y| < ~60
__device__ __forceinline__ float exp2_fast(float y) {
    float t = y + 12582912.0f;
    int   n = __float_as_int(t) - 0x4B400000;
    float f = y - (t - 12582912.0f);
    float p =              0.0013333558f;
    p = fmaf(p, f,         0.0096181291f);
    p = fmaf(p, f,         0.0555041087f);
    p = fmaf(p, f,         0.2402265069f);
    p = fmaf(p, f,         0.6931471806f);
    p = fmaf(p, f,         1.0f);
    return __int_as_float(__float_as_int(p) + (n << 23));
}

// ---- tf32 helpers (K1/K3, unchanged from R12/R13 — proven) ----------------
__device__ __forceinline__ void tf32_split(float a, uint32_t& hi, uint32_t& lo) {
    uint32_t h;
    asm("cvt.rna.tf32.f32 %0, %1;" : "=r"(h) : "f"(a));
    float r = a - __uint_as_float(h);
    uint32_t l;
    asm("cvt.rna.tf32.f32 %0, %1;" : "=r"(l) : "f"(r));
    hi = h; lo = l;
}
__device__ __forceinline__ void mma_tf32(float* c, const uint32_t* a, const uint32_t* b) {
    asm volatile(
        "mma.sync.aligned.m16n8k8.row.col.f32.tf32.tf32.f32 "
        "{%0,%1,%2,%3}, {%4,%5,%6,%7}, {%8,%9}, {%0,%1,%2,%3};"
        : "+f"(c[0]), "+f"(c[1]), "+f"(c[2]), "+f"(c[3])
        : "r"(a[0]), "r"(a[1]), "r"(a[2]), "r"(a[3]), "r"(b[0]), "r"(b[1]));
}

// ---- bf16 helpers (K2) ----------------------------------------------------
// pack {even k -> low half, odd k -> high half}
__device__ __forceinline__ uint32_t pack_bf16(float even, float odd) {
    uint32_t r;
    asm("cvt.rn.bf16x2.f32 %0, %1, %2;" : "=r"(r) : "f"(odd), "f"(even));
    return r;
}
__device__ __forceinline__ void pack_pair(float e, float o, uint32_t& h, uint32_t& l) {
    h = pack_bf16(e, o);
    float eh = __uint_as_float(h << 16);
    float oh = __uint_as_float(h & 0xFFFF0000u);
    l = pack_bf16(e - eh, o - oh);
}
__device__ __forceinline__ void mma_bf16(float* c, const uint32_t* a, const uint32_t* b) {
    asm volatile(
        "mma.sync.aligned.m16n8k16.row.col.f32.bf16.bf16.f32 "
        "{%0,%1,%2,%3}, {%4,%5,%6,%7}, {%8,%9}, {%0,%1,%2,%3};"
        : "+f"(c[0]), "+f"(c[1]), "+f"(c[2]), "+f"(c[3])
        : "r"(a[0]), "r"(a[1]), "r"(a[2]), "r"(a[3]), "r"(b[0]), "r"(b[1]));
}

// ---------------------------------------------------------------------------
// K1/K3: 3xTF32 GEMM (R12/R13-proven). Only change: V written TRANSPOSED.
// ---------------------------------------------------------------------------
constexpr int SSTR = 140;

template <int EPI>
__global__ __launch_bounds__(256, 2) void k_mma(
    const float* __restrict__ A,
    const float* __restrict__ B0,
    const float* __restrict__ B1,
    const float* __restrict__ bias,
    float* __restrict__ Cout)
{
    __shared__ float sA[8 * SSTR];
    __shared__ float sB[8 * SSTR];

    const int t    = threadIdx.x;
    const int bm   = blockIdx.x;
    const int bn   = blockIdx.y;
    const int lane = t & 31;
    const int warp = t >> 5;
    const int gid  = lane >> 2;
    const int tid4 = lane & 3;
    const int wm   = warp >> 2;
    const int wn   = warp & 3;
    const int lr   = t >> 1;
    const int lc   = (t & 1) << 2;

    const float* Ap   = (EPI == 1) ? (const float*)g_AO : A;
    const float* Arow = Ap + (bm * 128 + lr) * DIMS + lc;
    const int    ncol = bn * 128 + lr;
    const float* Brow;
    if (EPI == 0)
        Brow = (ncol < 512) ? (B0 + ncol * DIMS + lc)
                            : (B1 + (ncol - 512) * DIMS + lc);
    else
        Brow = B0 + ncol * DIMS + lc;

    float c[4][4][4];
#pragma unroll
    for (int mt = 0; mt < 4; mt++)
#pragma unroll
        for (int nt = 0; nt < 4; nt++)
#pragma unroll
            for (int e = 0; e < 4; e++) c[mt][nt][e] = 0.f;

    for (int kt = 0; kt < DIMS; kt += 8) {
        float4 av = *reinterpret_cast<const float4*>(Arow + kt);
        float4 bv = *reinterpret_cast<const float4*>(Brow + kt);
        __syncthreads();
        sA[(lc + 0) * SSTR + lr] = av.x; sA[(lc + 1) * SSTR + lr] = av.y;
        sA[(lc + 2) * SSTR + lr] = av.z; sA[(lc + 3) * SSTR + lr] = av.w;
        sB[(lc + 0) * SSTR + lr] = bv.x; sB[(lc + 1) * SSTR + lr] = bv.y;
        sB[(lc + 2) * SSTR + lr] = bv.z; sB[(lc + 3) * SSTR + lr] = bv.w;
        __syncthreads();

        uint32_t bh[4][2], bl[4][2];
#pragma unroll
        for (int nt = 0; nt < 4; nt++) {
            int cb = wn * 32 + nt * 8 + gid;
            tf32_split(sB[ tid4      * SSTR + cb], bh[nt][0], bl[nt][0]);
            tf32_split(sB[(tid4 + 4) * SSTR + cb], bh[nt][1], bl[nt][1]);
        }
#pragma unroll
        for (int mt = 0; mt < 4; mt++) {
            int rb = wm * 64 + mt * 16 + gid;
            uint32_t ah[4], al[4];
            tf32_split(sA[ tid4      * SSTR + rb    ], ah[0], al[0]);
            tf32_split(sA[ tid4      * SSTR + rb + 8], ah[1], al[1]);
            tf32_split(sA[(tid4 + 4) * SSTR + rb    ], ah[2], al[2]);
            tf32_split(sA[(tid4 + 4) * SSTR + rb + 8], ah[3], al[3]);
#pragma unroll
            for (int nt = 0; nt < 4; nt++) {
                mma_tf32(c[mt][nt], al, bh[nt]);
                mma_tf32(c[mt][nt], ah, bl[nt]);
                mma_tf32(c[mt][nt], ah, bh[nt]);
            }
        }
    }

#pragma unroll
    for (int mt = 0; mt < 4; mt++)
#pragma unroll
        for (int nt = 0; nt < 4; nt++) {
            int m0 = bm * 128 + wm * 64 + mt * 16 + gid;
            int n0 = bn * 128 + wn * 32 + nt * 8 + tid4 * 2;
#pragma unroll
            for (int rs = 0; rs < 2; rs++) {
                int   m  = m0 + rs * 8;
                float v0 = c[mt][nt][rs * 2 + 0];
                float v1 = c[mt][nt][rs * 2 + 1];
                int bidx = m >> 10;
                int n    = m & 1023;
                if (EPI == 0) {
                    int d = n0 & 63;
                    if (n0 < 256) {
                        int k = n0 >> 6;
                        *reinterpret_cast<float2*>(
                            &g_QS[(((bidx * NG + k) << 10) + n) * HD + d]) =
                            make_float2(v0 * 0.125f, v1 * 0.125f);
                    } else if (n0 < 512) {
                        int k = (n0 - 256) >> 6;
                        *reinterpret_cast<float2*>(
                            &g_KS[(((bidx * NG + k) << 10) + n) * HD + d]) =
                            make_float2(v0, v1);
                    } else {
                        int h = (n0 - 512) >> 6;
                        // TRANSPOSED V: g_VST[b][h][d][n]
                        g_VST[((bidx * NH + h) * HD + d    ) * SEQ + n] = v0;
                        g_VST[((bidx * NH + h) * HD + d + 1) * SEQ + n] = v1;
                    }
                } else {
                    *reinterpret_cast<float2*>(&Cout[m * DIMS + n0]) =
                        make_float2(v0 + bias[n0], v1 + bias[n0 + 1]);
                }
            }
        }
}

// ---------------------------------------------------------------------------
// K2: bf16 m16n8k16 flash attention, i-tile = 16, O in registers.
// grid (64, 8), 256 threads = 8 warps: warp = (hw = head 0..3, dh = half).
// Packed bf16x2 hi/lo smem (k-even in low half):
//   QP [4][16][36] pairs along d | KP [4][32][36] | Sf [4][16][36] fp32 |
//   EP [4][16][18] pairs along j | VP [4][64][18] pairs along j (from g_VST)
// ---------------------------------------------------------------------------
constexpr int W_QPH = 0;                       // 4*16*36 = 2304
constexpr int W_QPL = W_QPH + 2304;
constexpr int W_KPH = W_QPL + 2304;            // 4*32*36 = 4608
constexpr int W_KPL = W_KPH + 4608;
constexpr int W_SF  = W_KPL + 4608;            // 2304 (fp32)
constexpr int W_EPH = W_SF  + 2304;            // 4*16*18 = 1152
constexpr int W_EPL = W_EPH + 1152;
constexpr int W_VPH = W_EPL + 1152;            // 4*64*18 = 4608
constexpr int W_VPL = W_VPH + 4608;
constexpr int W_DEN = W_VPL + 4608;            // 12*16 = 192
constexpr int W_DRED= W_DEN + 192;             // 256
constexpr int W_MIX = W_DRED + 256;            // 48
constexpr int SM3_W = W_MIX + 48;              // 28144 words = 112576 B

__global__ __launch_bounds__(256, 2) void k_attn(const float* __restrict__ mix_logits)
{
    extern __shared__ float sm[];
    uint32_t* usm = reinterpret_cast<uint32_t*>(sm);
    uint32_t* QPH = usm + W_QPH;  uint32_t* QPL = usm + W_QPL;
    uint32_t* KPH = usm + W_KPH;  uint32_t* KPL = usm + W_KPL;
    float*    Sf  = sm  + W_SF;
    uint32_t* EPH = usm + W_EPH;  uint32_t* EPL = usm + W_EPL;
    uint32_t* VPH = usm + W_VPH;  uint32_t* VPL = usm + W_VPL;
    float*    den = sm + W_DEN;
    float*    dred= sm + W_DRED;
    float*    mixs= sm + W_MIX;

    const int t    = threadIdx.x;
    const int b    = blockIdx.y;
    const int i0   = blockIdx.x * 16;
    const int lane = t & 31;
    const int warp = t >> 5;
    const int gid  = lane >> 2;
    const int tig  = lane & 3;
    const int hw   = warp >> 1;
    const int dh   = warp & 1;

    if (t < NH) {
        float m0 = mix_logits[t * 4 + 0], m1 = mix_logits[t * 4 + 1];
        float m2 = mix_logits[t * 4 + 2], m3 = mix_logits[t * 4 + 3];
        float mx = fmaxf(fmaxf(m0, m1), fmaxf(m2, m3));
        float e0 = __expf(m0 - mx), e1 = __expf(m1 - mx);
        float e2 = __expf(m2 - mx), e3 = __expf(m3 - mx);
        float inv = 1.4426950408889634f / (e0 + e1 + e2 + e3);  // log2e / sum
        mixs[t * 4 + 0] = e0 * inv; mixs[t * 4 + 1] = e1 * inv;
        mixs[t * 4 + 2] = e2 * inv; mixs[t * 4 + 3] = e3 * inv;
    }
    if (t < 192) den[t] = 0.f;

    // Q pack (once): 4 heads x 16 rows x 64 d = 1024 float4
#pragma unroll
    for (int it = 0; it < 4; it++) {
        int e  = it * 256 + t;
        int k  = e >> 8, r = (e >> 4) & 15, d4 = (e & 15) << 2;
        float4 q = *reinterpret_cast<const float4*>(
            &g_QS[(((b * NG + k) << 10) + i0 + r) * HD + d4]);
        uint32_t h0, l0, h1, l1;
        pack_pair(q.x, q.y, h0, l0);
        pack_pair(q.z, q.w, h1, l1);
        int idx = k * 576 + r * 36 + (d4 >> 1);
        *reinterpret_cast<uint2*>(&QPH[idx]) = make_uint2(h0, h1);
        *reinterpret_cast<uint2*>(&QPL[idx]) = make_uint2(l0, l1);
    }
    __syncthreads();

    // E-phase thread map: 4 heads x 16 rows x 4 j-groups, 8 j per thread
    const int eh2 = t >> 6;          // head-in-group
    const int er  = (t >> 2) & 15;   // i row
    const int jp2 = t & 3;           // j octet selector (8 j values)

    // register O accumulators: cp[g][mt][nt][4]
    float cp[3][2][2][4];
#pragma unroll
    for (int g = 0; g < 3; g++)
#pragma unroll
        for (int mt = 0; mt < 2; mt++)
#pragma unroll
            for (int nt = 0; nt < 2; nt++)
#pragma unroll
                for (int e = 0; e < 4; e++) cp[g][mt][nt][e] = 0.f;

    for (int jt = 0; jt < SEQ; jt += 32) {
        // K pack: 4 heads x 32 j x 64 d = 2048 float4
#pragma unroll
        for (int it = 0; it < 8; it++) {
            int e  = it * 256 + t;
            int k  = e >> 9, r = (e >> 4) & 31, d4 = (e & 15) << 2;
            float4 kv = *reinterpret_cast<const float4*>(
                &g_KS[(((b * NG + k) << 10) + jt + r) * HD + d4]);
            uint32_t h0, l0, h1, l1;
            pack_pair(kv.x, kv.y, h0, l0);
            pack_pair(kv.z, kv.w, h1, l1);
            int idx = k * 1152 + r * 36 + (d4 >> 1);
            *reinterpret_cast<uint2*>(&KPH[idx]) = make_uint2(h0, h1);
            *reinterpret_cast<uint2*>(&KPL[idx]) = make_uint2(l0, l1);
        }
        __syncthreads();

        // S = Q K^T : M=16 i, N=32 j (this warp: 16 via dh), Kdim=64 d
        {
            float cs[2][4];
#pragma unroll
            for (int nt = 0; nt < 2; nt++)
#pragma unroll
                for (int e = 0; e < 4; e++) cs[nt][e] = 0.f;
            const uint32_t* qh = QPH + hw * 576;
            const uint32_t* ql = QPL + hw * 576;
            const uint32_t* kh = KPH + hw * 1152;
            const uint32_t* kl = KPL + hw * 1152;
#pragma unroll
            for (int ks = 0; ks < 4; ks++) {
                int kb = ks * 8;
                uint32_t ah[4], al[4];
                ah[0] = qh[ gid      * 36 + kb + tig    ];
                ah[1] = qh[(gid + 8) * 36 + kb + tig    ];
                ah[2] = qh[ gid      * 36 + kb + tig + 4];
                ah[3] = qh[(gid + 8) * 36 + kb + tig + 4];
                al[0] = ql[ gid      * 36 + kb + tig    ];
                al[1] = ql[(gid + 8) * 36 + kb + tig    ];
                al[2] = ql[ gid      * 36 + kb + tig + 4];
                al[3] = ql[(gid + 8) * 36 + kb + tig + 4];
#pragma unroll
                for (int nt = 0; nt < 2; nt++) {
                    int n = dh * 16 + nt * 8 + gid;
                    uint32_t bh2[2], bl2[2];
                    bh2[0] = kh[n * 36 + kb + tig    ];
                    bh2[1] = kh[n * 36 + kb + tig + 4];
                    bl2[0] = kl[n * 36 + kb + tig    ];
                    bl2[1] = kl[n * 36 + kb + tig + 4];
                    mma_bf16(cs[nt], al, bh2);
                    mma_bf16(cs[nt], ah, bl2);
                    mma_bf16(cs[nt], ah, bh2);
                }
            }
            float* sb = Sf + hw * 576;
#pragma unroll
            for (int nt = 0; nt < 2; nt++) {
                int cb = dh * 16 + nt * 8 + 2 * tig;
                *reinterpret_cast<float2*>(&sb[ gid      * 36 + cb]) =
                    make_float2(cs[nt][0], cs[nt][1]);
                *reinterpret_cast<float2*>(&sb[(gid + 8) * 36 + cb]) =
                    make_float2(cs[nt][2], cs[nt][3]);
            }
        }
        __syncthreads();

#pragma unroll
        for (int g = 0; g < 3; g++) {
            // V pack (from transposed g_VST): 4 heads x 64 d x 32 j
#pragma unroll
            for (int it = 0; it < 8; it++) {
                int e  = it * 256 + t;
                int hs = e >> 9, d = (e >> 3) & 63, j4 = (e & 7) << 2;
                float4 vv = *reinterpret_cast<const float4*>(
                    &g_VST[((b * NH + g * 4 + hs) * HD + d) * SEQ + jt + j4]);
                uint32_t h0, l0, h1, l1;
                pack_pair(vv.x, vv.y, h0, l0);
                pack_pair(vv.z, vv.w, h1, l1);
                int idx = hs * 1152 + d * 18 + (j4 >> 1);
                VPH[idx] = h0; VPH[idx + 1] = h1;
                VPL[idx] = l0; VPL[idx + 1] = l1;
            }
            // E = 2^(mixed log2 logits): 8 j per thread -> FULL j coverage
            {
                int hh = g * 4 + eh2;
                float m0 = mixs[hh * 4 + 0], m1 = mixs[hh * 4 + 1];
                float m2 = mixs[hh * 4 + 2], m3 = mixs[hh * 4 + 3];
                int so  = er * 36 + 8 * jp2;
                int idx = eh2 * 288 + er * 18 + 4 * jp2;
                float psum = 0.f;
#pragma unroll
                for (int q = 0; q < 2; q++) {
                    int o = so + q * 4;
                    float4 s0 = *reinterpret_cast<const float4*>(&Sf[       o]);
                    float4 s1 = *reinterpret_cast<const float4*>(&Sf[ 576 + o]);
                    float4 s2 = *reinterpret_cast<const float4*>(&Sf[1152 + o]);
                    float4 s3 = *reinterpret_cast<const float4*>(&Sf[1728 + o]);
                    float e0 = exp2_fast(m0 * s0.x + m1 * s1.x + m2 * s2.x + m3 * s3.x);
                    float e1 = exp2_fast(m0 * s0.y + m1 * s1.y + m2 * s2.y + m3 * s3.y);
                    float e2 = exp2_fast(m0 * s0.z + m1 * s1.z + m2 * s2.z + m3 * s3.z);
                    float e3 = exp2_fast(m0 * s0.w + m1 * s1.w + m2 * s2.w + m3 * s3.w);
                    uint32_t h0, l0, h1, l1;
                    pack_pair(e0, e1, h0, l0);
                    pack_pair(e2, e3, h1, l1);
                    EPH[idx + 2 * q] = h0; EPH[idx + 2 * q + 1] = h1;
                    EPL[idx + 2 * q] = l0; EPL[idx + 2 * q + 1] = l1;
                    psum += e0 + e1 + e2 + e3;
                }
                dred[t] = psum;
            }
            __syncthreads();
            if ((t & 3) == 0)
                den[(g * 4 + eh2) * 16 + er] +=
                    dred[t] + dred[t + 1] + dred[t + 2] + dred[t + 3];
            // PV: O^T = V^T E^T : M=64 d (warp: 32 via dh), N=16 i, Kdim=32 j
            {
                const uint32_t* vh = VPH + hw * 1152;
                const uint32_t* vl = VPL + hw * 1152;
                const uint32_t* eh = EPH + hw * 288;
                const uint32_t* el = EPL + hw * 288;
#pragma unroll
                for (int ks = 0; ks < 2; ks++) {
                    int jb = ks * 8;
                    uint32_t bh2[2][2], bl2[2][2];
#pragma unroll
                    for (int nt = 0; nt < 2; nt++) {
                        int ic = nt * 8 + gid;
                        bh2[nt][0] = eh[ic * 18 + jb + tig    ];
                        bh2[nt][1] = eh[ic * 18 + jb + tig + 4];
                        bl2[nt][0] = el[ic * 18 + jb + tig    ];
                        bl2[nt][1] = el[ic * 18 + jb + tig + 4];
                    }
#pragma unroll
                    for (int mt = 0; mt < 2; mt++) {
                        int dr = dh * 32 + mt * 16 + gid;
                        uint32_t ah[4], al[4];
                        ah[0] = vh[ dr      * 18 + jb + tig    ];
                        ah[1] = vh[(dr + 8) * 18 + jb + tig    ];
                        ah[2] = vh[ dr      * 18 + jb + tig + 4];
                        ah[3] = vh[(dr + 8) * 18 + jb + tig + 4];
                        al[0] = vl[ dr      * 18 + jb + tig    ];
                        al[1] = vl[(dr + 8) * 18 + jb + tig    ];
                        al[2] = vl[ dr      * 18 + jb + tig + 4];
                        al[3] = vl[(dr + 8) * 18 + jb + tig + 4];
#pragma unroll
                        for (int nt = 0; nt < 2; nt++) {
                            mma_bf16(cp[g][mt][nt], al, bh2[nt]);
                            mma_bf16(cp[g][mt][nt], ah, bl2[nt]);
                            mma_bf16(cp[g][mt][nt], ah, bh2[nt]);
                        }
                    }
                }
            }
            __syncthreads();
        }
    }

    // write O: cp[g][mt][nt] element (d = dh*32+mt*16+gid(+8), i = nt*8+2tig(+1))
#pragma unroll
    for (int g = 0; g < 3; g++) {
        int hh = g * 4 + hw;
#pragma unroll
        for (int mt = 0; mt < 2; mt++)
#pragma unroll
            for (int nt = 0; nt < 2; nt++) {
                int d0 = dh * 32 + mt * 16 + gid;
                int ic = nt * 8 + 2 * tig;
                float iv0 = 1.f / den[hh * 16 + ic];
                float iv1 = 1.f / den[hh * 16 + ic + 1];
                int base0 = ((b << 10) + i0 + ic    ) * DIMS + hh * 64;
                int base1 = ((b << 10) + i0 + ic + 1) * DIMS + hh * 64;
                g_AO[base0 + d0    ] = cp[g][mt][nt][0] * iv0;
                g_AO[base1 + d0    ] = cp[g][mt][nt][1] * iv1;
                g_AO[base0 + d0 + 8] = cp[g][mt][nt][2] * iv0;
                g_AO[base1 + d0 + 8] = cp[g][mt][nt][3] * iv1;
            }
    }
}

// ---------------------------------------------------------------------------
extern "C" void kernel_launch(void* const* d_in, const int* in_sizes, int n_in,
                              void* d_out, int out_size)
{
    const float* x    = (const float*)d_in[0];
    const float* wqkv = (const float*)d_in[1];
    const float* mixl = (const float*)d_in[2];
    const float* wv   = (const float*)d_in[3];
    const float* wpr  = (const float*)d_in[4];
    const float* bpr  = (const float*)d_in[5];
    float* out = (float*)d_out;

    cudaFuncSetAttribute(k_attn, cudaFuncAttributeMaxDynamicSharedMemorySize,
                         SM3_W * (int)sizeof(float));

    // K1: fused QK + V projections, 3xTF32 (V stored transposed)
    k_mma<0><<<dim3(64, 10), 256>>>(x, wqkv, wv, nullptr, nullptr);
    // K2: flash attention, bf16 m16n8k16 3-term, O in registers
    k_attn<<<dim3(64, 8), 256, SM3_W * (int)sizeof(float)>>>(mixl);
    // K3: output projection + bias, 3xTF32
    k_mma<1><<<dim3(64, 6), 256>>>(nullptr, wpr, nullptr, bpr, out);
}

// round 17
// speedup vs baseline: 1.9200x; 1.2256x over previous
#include <cuda_runtime.h>
#include <cstdint>

// ---------------------------------------------------------------------------
// FiSHAttention — round 17.
// R16: 1145us (K2 bf16 m16n8k16 pre-packed: ~1036 -> ~600us; theory validated).
// K1/K3 still tf32 3-term with per-use cvt chains (alu 27.4%) — same disease
// K2 had. This round: K1/K3 -> bf16 m16n8k16 3-term with per-kt pre-packed
// bf16x2 hi/lo smem (stride 12, conflict-free frag loads). MMA instr count
// halves on a 2x-rate pipe; aux ops drop ~4.5x. K2 byte-identical to R16.
// ---------------------------------------------------------------------------

constexpr int BATCH = 8;
constexpr int SEQ   = 1024;
constexpr int DIMS  = 768;
constexpr int NH    = 12;
constexpr int NG    = 4;
constexpr int HD    = 64;
constexpr int TOK   = BATCH * SEQ;

__device__ float g_QS[BATCH * NG * SEQ * HD];    // (b,k,n,d) scaled 1/8
__device__ float g_KS[BATCH * NG * SEQ * HD];    // (b,k,n,d)
__device__ float g_VST[BATCH * NH * HD * SEQ];   // (b,h,d,n)  TRANSPOSED
__device__ float g_AO[TOK * DIMS];               // (token, h*64+d)

// fast 2^y on fma/alu pipes (no MUFU), |y| < ~60
__device__ __forceinline__ float exp2_fast(float y) {
    float t = y + 12582912.0f;
    int   n = __float_as_int(t) - 0x4B400000;
    float f = y - (t - 12582912.0f);
    float p =              0.0013333558f;
    p = fmaf(p, f,         0.0096181291f);
    p = fmaf(p, f,         0.0555041087f);
    p = fmaf(p, f,         0.2402265069f);
    p = fmaf(p, f,         0.6931471806f);
    p = fmaf(p, f,         1.0f);
    return __int_as_float(__float_as_int(p) + (n << 23));
}

// ---- bf16 helpers ---------------------------------------------------------
// pack {even k -> low half, odd k -> high half}
__device__ __forceinline__ uint32_t pack_bf16(float even, float odd) {
    uint32_t r;
    asm("cvt.rn.bf16x2.f32 %0, %1, %2;" : "=r"(r) : "f"(odd), "f"(even));
    return r;
}
__device__ __forceinline__ void pack_pair(float e, float o, uint32_t& h, uint32_t& l) {
    h = pack_bf16(e, o);
    float eh = __uint_as_float(h << 16);
    float oh = __uint_as_float(h & 0xFFFF0000u);
    l = pack_bf16(e - eh, o - oh);
}
__device__ __forceinline__ void mma_bf16(float* c, const uint32_t* a, const uint32_t* b) {
    asm volatile(
        "mma.sync.aligned.m16n8k16.row.col.f32.bf16.bf16.f32 "
        "{%0,%1,%2,%3}, {%4,%5,%6,%7}, {%8,%9}, {%0,%1,%2,%3};"
        : "+f"(c[0]), "+f"(c[1]), "+f"(c[2]), "+f"(c[3])
        : "r"(a[0]), "r"(a[1]), "r"(a[2]), "r"(a[3]), "r"(b[0]), "r"(b[1]));
}

// ---------------------------------------------------------------------------
// K1/K3: bf16 m16n8k16 3-term GEMM. BM=BN=128, BK=16, 8 warps (2x4),
// warp tile 64x32 = 4x4 MMAs per kt. Operands packed once per kt into
// bf16x2 hi/lo smem, stride 12 (8 pairs + 4 pad): frag banks 12*gid+tig
// all distinct mod 32. Epilogue identical to R12-R16 (C frag layout same).
// EPI==0: A=x, B=cat(w_qkv[0:512], w_v), scatter QS/KS/VST(transposed)
// EPI==1: A=g_AO, B=w_proj, C=out + bias
// ---------------------------------------------------------------------------
constexpr int PSTR = 12;

template <int EPI>
__global__ __launch_bounds__(256, 2) void k_mma(
    const float* __restrict__ A,
    const float* __restrict__ B0,
    const float* __restrict__ B1,
    const float* __restrict__ bias,
    float* __restrict__ Cout)
{
    __shared__ uint32_t APH[128 * PSTR], APL[128 * PSTR];
    __shared__ uint32_t BPH[128 * PSTR], BPL[128 * PSTR];

    const int t    = threadIdx.x;
    const int bm   = blockIdx.x;
    const int bn   = blockIdx.y;
    const int lane = t & 31;
    const int warp = t >> 5;
    const int gid  = lane >> 2;
    const int tig  = lane & 3;
    const int wm   = warp >> 2;
    const int wn   = warp & 3;
    const int lr   = t >> 1;        // 0..127 loader row
    const int lh   = t & 1;         // k half (8 floats each)

    const float* Ap   = (EPI == 1) ? (const float*)g_AO : A;
    const float* Arow = Ap + (bm * 128 + lr) * DIMS + lh * 8;
    const int    ncol = bn * 128 + lr;
    const float* Brow;
    if (EPI == 0)
        Brow = (ncol < 512) ? (B0 + ncol * DIMS + lh * 8)
                            : (B1 + (ncol - 512) * DIMS + lh * 8);
    else
        Brow = B0 + ncol * DIMS + lh * 8;

    float c[4][4][4];
#pragma unroll
    for (int mt = 0; mt < 4; mt++)
#pragma unroll
        for (int nt = 0; nt < 4; nt++)
#pragma unroll
            for (int e = 0; e < 4; e++) c[mt][nt][e] = 0.f;

    const int ib = lr * PSTR + lh * 4;

    for (int kt = 0; kt < DIMS; kt += 16) {
        float4 a0 = *reinterpret_cast<const float4*>(Arow + kt);
        float4 a1 = *reinterpret_cast<const float4*>(Arow + kt + 4);
        float4 b0 = *reinterpret_cast<const float4*>(Brow + kt);
        float4 b1 = *reinterpret_cast<const float4*>(Brow + kt + 4);
        __syncthreads();
        pack_pair(a0.x, a0.y, APH[ib + 0], APL[ib + 0]);
        pack_pair(a0.z, a0.w, APH[ib + 1], APL[ib + 1]);
        pack_pair(a1.x, a1.y, APH[ib + 2], APL[ib + 2]);
        pack_pair(a1.z, a1.w, APH[ib + 3], APL[ib + 3]);
        pack_pair(b0.x, b0.y, BPH[ib + 0], BPL[ib + 0]);
        pack_pair(b0.z, b0.w, BPH[ib + 1], BPL[ib + 1]);
        pack_pair(b1.x, b1.y, BPH[ib + 2], BPL[ib + 2]);
        pack_pair(b1.z, b1.w, BPH[ib + 3], BPL[ib + 3]);
        __syncthreads();

        uint32_t bh[4][2], bl[4][2];
#pragma unroll
        for (int nt = 0; nt < 4; nt++) {
            int cb = (wn * 32 + nt * 8 + gid) * PSTR;
            bh[nt][0] = BPH[cb + tig];     bh[nt][1] = BPH[cb + tig + 4];
            bl[nt][0] = BPL[cb + tig];     bl[nt][1] = BPL[cb + tig + 4];
        }
#pragma unroll
        for (int mt = 0; mt < 4; mt++) {
            int r0 = (wm * 64 + mt * 16 + gid) * PSTR;
            int r1 = r0 + 8 * PSTR;
            uint32_t ah[4], al[4];
            ah[0] = APH[r0 + tig];     ah[1] = APH[r1 + tig];
            ah[2] = APH[r0 + tig + 4]; ah[3] = APH[r1 + tig + 4];
            al[0] = APL[r0 + tig];     al[1] = APL[r1 + tig];
            al[2] = APL[r0 + tig + 4]; al[3] = APL[r1 + tig + 4];
#pragma unroll
            for (int nt = 0; nt < 4; nt++) {
                mma_bf16(c[mt][nt], al, bh[nt]);   // lo*hi
                mma_bf16(c[mt][nt], ah, bl[nt]);   // hi*lo
                mma_bf16(c[mt][nt], ah, bh[nt]);   // hi*hi
            }
        }
    }

    // epilogue: thread owns rows {m0, m0+8}, col pair {n0, n0+1} per (mt,nt)
#pragma unroll
    for (int mt = 0; mt < 4; mt++)
#pragma unroll
        for (int nt = 0; nt < 4; nt++) {
            int m0 = bm * 128 + wm * 64 + mt * 16 + gid;
            int n0 = bn * 128 + wn * 32 + nt * 8 + tig * 2;
#pragma unroll
            for (int rs = 0; rs < 2; rs++) {
                int   m  = m0 + rs * 8;
                float v0 = c[mt][nt][rs * 2 + 0];
                float v1 = c[mt][nt][rs * 2 + 1];
                int bidx = m >> 10;
                int n    = m & 1023;
                if (EPI == 0) {
                    int d = n0 & 63;
                    if (n0 < 256) {
                        int k = n0 >> 6;
                        *reinterpret_cast<float2*>(
                            &g_QS[(((bidx * NG + k) << 10) + n) * HD + d]) =
                            make_float2(v0 * 0.125f, v1 * 0.125f);
                    } else if (n0 < 512) {
                        int k = (n0 - 256) >> 6;
                        *reinterpret_cast<float2*>(
                            &g_KS[(((bidx * NG + k) << 10) + n) * HD + d]) =
                            make_float2(v0, v1);
                    } else {
                        int h = (n0 - 512) >> 6;
                        // TRANSPOSED V: g_VST[b][h][d][n]
                        g_VST[((bidx * NH + h) * HD + d    ) * SEQ + n] = v0;
                        g_VST[((bidx * NH + h) * HD + d + 1) * SEQ + n] = v1;
                    }
                } else {
                    *reinterpret_cast<float2*>(&Cout[m * DIMS + n0]) =
                        make_float2(v0 + bias[n0], v1 + bias[n0 + 1]);
                }
            }
        }
}

// ---------------------------------------------------------------------------
// K2: bf16 m16n8k16 flash attention (byte-identical to R16 — passed 1145us).
// ---------------------------------------------------------------------------
constexpr int W_QPH = 0;                       // 4*16*36 = 2304
constexpr int W_QPL = W_QPH + 2304;
constexpr int W_KPH = W_QPL + 2304;            // 4*32*36 = 4608
constexpr int W_KPL = W_KPH + 4608;
constexpr int W_SF  = W_KPL + 4608;            // 2304 (fp32)
constexpr int W_EPH = W_SF  + 2304;            // 4*16*18 = 1152
constexpr int W_EPL = W_EPH + 1152;
constexpr int W_VPH = W_EPL + 1152;            // 4*64*18 = 4608
constexpr int W_VPL = W_VPH + 4608;
constexpr int W_DEN = W_VPL + 4608;            // 12*16 = 192
constexpr int W_DRED= W_DEN + 192;             // 256
constexpr int W_MIX = W_DRED + 256;            // 48
constexpr int SM3_W = W_MIX + 48;              // 28144 words = 112576 B

__global__ __launch_bounds__(256, 2) void k_attn(const float* __restrict__ mix_logits)
{
    extern __shared__ float sm[];
    uint32_t* usm = reinterpret_cast<uint32_t*>(sm);
    uint32_t* QPH = usm + W_QPH;  uint32_t* QPL = usm + W_QPL;
    uint32_t* KPH = usm + W_KPH;  uint32_t* KPL = usm + W_KPL;
    float*    Sf  = sm  + W_SF;
    uint32_t* EPH = usm + W_EPH;  uint32_t* EPL = usm + W_EPL;
    uint32_t* VPH = usm + W_VPH;  uint32_t* VPL = usm + W_VPL;
    float*    den = sm + W_DEN;
    float*    dred= sm + W_DRED;
    float*    mixs= sm + W_MIX;

    const int t    = threadIdx.x;
    const int b    = blockIdx.y;
    const int i0   = blockIdx.x * 16;
    const int lane = t & 31;
    const int warp = t >> 5;
    const int gid  = lane >> 2;
    const int tig  = lane & 3;
    const int hw   = warp >> 1;
    const int dh   = warp & 1;

    if (t < NH) {
        float m0 = mix_logits[t * 4 + 0], m1 = mix_logits[t * 4 + 1];
        float m2 = mix_logits[t * 4 + 2], m3 = mix_logits[t * 4 + 3];
        float mx = fmaxf(fmaxf(m0, m1), fmaxf(m2, m3));
        float e0 = __expf(m0 - mx), e1 = __expf(m1 - mx);
        float e2 = __expf(m2 - mx), e3 = __expf(m3 - mx);
        float inv = 1.4426950408889634f / (e0 + e1 + e2 + e3);  // log2e / sum
        mixs[t * 4 + 0] = e0 * inv; mixs[t * 4 + 1] = e1 * inv;
        mixs[t * 4 + 2] = e2 * inv; mixs[t * 4 + 3] = e3 * inv;
    }
    if (t < 192) den[t] = 0.f;

    // Q pack (once): 4 heads x 16 rows x 64 d = 1024 float4
#pragma unroll
    for (int it = 0; it < 4; it++) {
        int e  = it * 256 + t;
        int k  = e >> 8, r = (e >> 4) & 15, d4 = (e & 15) << 2;
        float4 q = *reinterpret_cast<const float4*>(
            &g_QS[(((b * NG + k) << 10) + i0 + r) * HD + d4]);
        uint32_t h0, l0, h1, l1;
        pack_pair(q.x, q.y, h0, l0);
        pack_pair(q.z, q.w, h1, l1);
        int idx = k * 576 + r * 36 + (d4 >> 1);
        *reinterpret_cast<uint2*>(&QPH[idx]) = make_uint2(h0, h1);
        *reinterpret_cast<uint2*>(&QPL[idx]) = make_uint2(l0, l1);
    }
    __syncthreads();

    // E-phase thread map: 4 heads x 16 rows x 4 j-groups, 8 j per thread
    const int eh2 = t >> 6;          // head-in-group
    const int er  = (t >> 2) & 15;   // i row
    const int jp2 = t & 3;           // j octet selector (8 j values)

    // register O accumulators: cp[g][mt][nt][4]
    float cp[3][2][2][4];
#pragma unroll
    for (int g = 0; g < 3; g++)
#pragma unroll
        for (int mt = 0; mt < 2; mt++)
#pragma unroll
            for (int nt = 0; nt < 2; nt++)
#pragma unroll
                for (int e = 0; e < 4; e++) cp[g][mt][nt][e] = 0.f;

    for (int jt = 0; jt < SEQ; jt += 32) {
        // K pack: 4 heads x 32 j x 64 d = 2048 float4
#pragma unroll
        for (int it = 0; it < 8; it++) {
            int e  = it * 256 + t;
            int k  = e >> 9, r = (e >> 4) & 31, d4 = (e & 15) << 2;
            float4 kv = *reinterpret_cast<const float4*>(
                &g_KS[(((b * NG + k) << 10) + jt + r) * HD + d4]);
            uint32_t h0, l0, h1, l1;
            pack_pair(kv.x, kv.y, h0, l0);
            pack_pair(kv.z, kv.w, h1, l1);
            int idx = k * 1152 + r * 36 + (d4 >> 1);
            *reinterpret_cast<uint2*>(&KPH[idx]) = make_uint2(h0, h1);
            *reinterpret_cast<uint2*>(&KPL[idx]) = make_uint2(l0, l1);
        }
        __syncthreads();

        // S = Q K^T : M=16 i, N=32 j (this warp: 16 via dh), Kdim=64 d
        {
            float cs[2][4];
#pragma unroll
            for (int nt = 0; nt < 2; nt++)
#pragma unroll
                for (int e = 0; e < 4; e++) cs[nt][e] = 0.f;
            const uint32_t* qh = QPH + hw * 576;
            const uint32_t* ql = QPL + hw * 576;
            const uint32_t* kh = KPH + hw * 1152;
            const uint32_t* kl = KPL + hw * 1152;
#pragma unroll
            for (int ks = 0; ks < 4; ks++) {
                int kb = ks * 8;
                uint32_t ah[4], al[4];
                ah[0] = qh[ gid      * 36 + kb + tig    ];
                ah[1] = qh[(gid + 8) * 36 + kb + tig    ];
                ah[2] = qh[ gid      * 36 + kb + tig + 4];
                ah[3] = qh[(gid + 8) * 36 + kb + tig + 4];
                al[0] = ql[ gid      * 36 + kb + tig    ];
                al[1] = ql[(gid + 8) * 36 + kb + tig    ];
                al[2] = ql[ gid      * 36 + kb + tig + 4];
                al[3] = ql[(gid + 8) * 36 + kb + tig + 4];
#pragma unroll
                for (int nt = 0; nt < 2; nt++) {
                    int n = dh * 16 + nt * 8 + gid;
                    uint32_t bh2[2], bl2[2];
                    bh2[0] = kh[n * 36 + kb + tig    ];
                    bh2[1] = kh[n * 36 + kb + tig + 4];
                    bl2[0] = kl[n * 36 + kb + tig    ];
                    bl2[1] = kl[n * 36 + kb + tig + 4];
                    mma_bf16(cs[nt], al, bh2);
                    mma_bf16(cs[nt], ah, bl2);
                    mma_bf16(cs[nt], ah, bh2);
                }
            }
            float* sb = Sf + hw * 576;
#pragma unroll
            for (int nt = 0; nt < 2; nt++) {
                int cb = dh * 16 + nt * 8 + 2 * tig;
                *reinterpret_cast<float2*>(&sb[ gid      * 36 + cb]) =
                    make_float2(cs[nt][0], cs[nt][1]);
                *reinterpret_cast<float2*>(&sb[(gid + 8) * 36 + cb]) =
                    make_float2(cs[nt][2], cs[nt][3]);
            }
        }
        __syncthreads();

#pragma unroll
        for (int g = 0; g < 3; g++) {
            // V pack (from transposed g_VST): 4 heads x 64 d x 32 j
#pragma unroll
            for (int it = 0; it < 8; it++) {
                int e  = it * 256 + t;
                int hs = e >> 9, d = (e >> 3) & 63, j4 = (e & 7) << 2;
                float4 vv = *reinterpret_cast<const float4*>(
                    &g_VST[((b * NH + g * 4 + hs) * HD + d) * SEQ + jt + j4]);
                uint32_t h0, l0, h1, l1;
                pack_pair(vv.x, vv.y, h0, l0);
                pack_pair(vv.z, vv.w, h1, l1);
                int idx = hs * 1152 + d * 18 + (j4 >> 1);
                VPH[idx] = h0; VPH[idx + 1] = h1;
                VPL[idx] = l0; VPL[idx + 1] = l1;
            }
            // E = 2^(mixed log2 logits): 8 j per thread -> FULL j coverage
            {
                int hh = g * 4 + eh2;
                float m0 = mixs[hh * 4 + 0], m1 = mixs[hh * 4 + 1];
                float m2 = mixs[hh * 4 + 2], m3 = mixs[hh * 4 + 3];
                int so  = er * 36 + 8 * jp2;
                int idx = eh2 * 288 + er * 18 + 4 * jp2;
                float psum = 0.f;
#pragma unroll
                for (int q = 0; q < 2; q++) {
                    int o = so + q * 4;
                    float4 s0 = *reinterpret_cast<const float4*>(&Sf[       o]);
                    float4 s1 = *reinterpret_cast<const float4*>(&Sf[ 576 + o]);
                    float4 s2 = *reinterpret_cast<const float4*>(&Sf[1152 + o]);
                    float4 s3 = *reinterpret_cast<const float4*>(&Sf[1728 + o]);
                    float e0 = exp2_fast(m0 * s0.x + m1 * s1.x + m2 * s2.x + m3 * s3.x);
                    float e1 = exp2_fast(m0 * s0.y + m1 * s1.y + m2 * s2.y + m3 * s3.y);
                    float e2 = exp2_fast(m0 * s0.z + m1 * s1.z + m2 * s2.z + m3 * s3.z);
                    float e3 = exp2_fast(m0 * s0.w + m1 * s1.w + m2 * s2.w + m3 * s3.w);
                    uint32_t h0, l0, h1, l1;
                    pack_pair(e0, e1, h0, l0);
                    pack_pair(e2, e3, h1, l1);
                    EPH[idx + 2 * q] = h0; EPH[idx + 2 * q + 1] = h1;
                    EPL[idx + 2 * q] = l0; EPL[idx + 2 * q + 1] = l1;
                    psum += e0 + e1 + e2 + e3;
                }
                dred[t] = psum;
            }
            __syncthreads();
            if ((t & 3) == 0)
                den[(g * 4 + eh2) * 16 + er] +=
                    dred[t] + dred[t + 1] + dred[t + 2] + dred[t + 3];
            // PV: O^T = V^T E^T : M=64 d (warp: 32 via dh), N=16 i, Kdim=32 j
            {
                const uint32_t* vh = VPH + hw * 1152;
                const uint32_t* vl = VPL + hw * 1152;
                const uint32_t* eh = EPH + hw * 288;
                const uint32_t* el = EPL + hw * 288;
#pragma unroll
                for (int ks = 0; ks < 2; ks++) {
                    int jb = ks * 8;
                    uint32_t bh2[2][2], bl2[2][2];
#pragma unroll
                    for (int nt = 0; nt < 2; nt++) {
                        int ic = nt * 8 + gid;
                        bh2[nt][0] = eh[ic * 18 + jb + tig    ];
                        bh2[nt][1] = eh[ic * 18 + jb + tig + 4];
                        bl2[nt][0] = el[ic * 18 + jb + tig    ];
                        bl2[nt][1] = el[ic * 18 + jb + tig + 4];
                    }
#pragma unroll
                    for (int mt = 0; mt < 2; mt++) {
                        int dr = dh * 32 + mt * 16 + gid;
                        uint32_t ah[4], al[4];
                        ah[0] = vh[ dr      * 18 + jb + tig    ];
                        ah[1] = vh[(dr + 8) * 18 + jb + tig    ];
                        ah[2] = vh[ dr      * 18 + jb + tig + 4];
                        ah[3] = vh[(dr + 8) * 18 + jb + tig + 4];
                        al[0] = vl[ dr      * 18 + jb + tig    ];
                        al[1] = vl[(dr + 8) * 18 + jb + tig    ];
                        al[2] = vl[ dr      * 18 + jb + tig + 4];
                        al[3] = vl[(dr + 8) * 18 + jb + tig + 4];
#pragma unroll
                        for (int nt = 0; nt < 2; nt++) {
                            mma_bf16(cp[g][mt][nt], al, bh2[nt]);
                            mma_bf16(cp[g][mt][nt], ah, bl2[nt]);
                            mma_bf16(cp[g][mt][nt], ah, bh2[nt]);
                        }
                    }
                }
            }
            __syncthreads();
        }
    }

    // write O: cp[g][mt][nt] element (d = dh*32+mt*16+gid(+8), i = nt*8+2tig(+1))
#pragma unroll
    for (int g = 0; g < 3; g++) {
        int hh = g * 4 + hw;
#pragma unroll
        for (int mt = 0; mt < 2; mt++)
#pragma unroll
            for (int nt = 0; nt < 2; nt++) {
                int d0 = dh * 32 + mt * 16 + gid;
                int ic = nt * 8 + 2 * tig;
                float iv0 = 1.f / den[hh * 16 + ic];
                float iv1 = 1.f / den[hh * 16 + ic + 1];
                int base0 = ((b << 10) + i0 + ic    ) * DIMS + hh * 64;
                int base1 = ((b << 10) + i0 + ic + 1) * DIMS + hh * 64;
                g_AO[base0 + d0    ] = cp[g][mt][nt][0] * iv0;
                g_AO[base1 + d0    ] = cp[g][mt][nt][1] * iv1;
                g_AO[base0 + d0 + 8] = cp[g][mt][nt][2] * iv0;
                g_AO[base1 + d0 + 8] = cp[g][mt][nt][3] * iv1;
            }
    }
}

// ---------------------------------------------------------------------------
extern "C" void kernel_launch(void* const* d_in, const int* in_sizes, int n_in,
                              void* d_out, int out_size)
{
    const float* x    = (const float*)d_in[0];
    const float* wqkv = (const float*)d_in[1];
    const float* mixl = (const float*)d_in[2];
    const float* wv   = (const float*)d_in[3];
    const float* wpr  = (const float*)d_in[4];
    const float* bpr  = (const float*)d_in[5];
    float* out = (float*)d_out;

    cudaFuncSetAttribute(k_attn, cudaFuncAttributeMaxDynamicSharedMemorySize,
                         SM3_W * (int)sizeof(float));

    // K1: fused QK + V projections, bf16 m16n8k16 3-term (V transposed)
    k_mma<0><<<dim3(64, 10), 256>>>(x, wqkv, wv, nullptr, nullptr);
    // K2: flash attention, bf16 m16n8k16 3-term, O in registers
    k_attn<<<dim3(64, 8), 256, SM3_W * (int)sizeof(float)>>>(mixl);
    // K3: output projection + bias, bf16 m16n8k16 3-term
    k_mma<1><<<dim3(64, 6), 256>>>(nullptr, wpr, nullptr, bpr, out);
}